// round 3
// baseline (speedup 1.0000x reference)
#include <cuda_runtime.h>
#include <math.h>
#include <stdint.h>

// Problem constants
#define Bz 2
#define Sq 1024
#define Dm 1024
#define Hh 16
#define Ll 6
#define Vv 50257
#define HDm 64
#define MROWS (Bz * Sq)   // 2048
#define FFd (4 * Dm)      // 4096

// Scratch
__device__ float g_x[MROWS * Dm];
__device__ float g_h[MROWS * Dm];
__device__ float g_q[MROWS * Dm];
__device__ float g_k[MROWS * Dm];
__device__ float g_v[MROWS * Dm];
__device__ float g_att[MROWS * Dm];
__device__ float g_ff[MROWS * FFd];

// ---------------------------------------------------------------------------
// Helpers
// ---------------------------------------------------------------------------
__device__ __forceinline__ uint32_t f2tf(float x) {
    uint32_t r;
    asm("cvt.rna.tf32.f32 %0, %1;" : "=r"(r) : "f"(x));
    return r;
}

__device__ __forceinline__ void cpasync16(void* smem_dst, const void* gsrc) {
    uint32_t d = (uint32_t)__cvta_generic_to_shared(smem_dst);
    asm volatile("cp.async.ca.shared.global [%0], [%1], 16;" :: "r"(d), "l"(gsrc));
}
#define CP_COMMIT() asm volatile("cp.async.commit_group;")
#define CP_WAIT1()  asm volatile("cp.async.wait_group 1;")
#define CP_WAIT0()  asm volatile("cp.async.wait_group 0;")

__device__ __forceinline__ void mma_tf32(float* c, const uint32_t* a, const uint32_t* b) {
    asm volatile(
        "mma.sync.aligned.m16n8k8.row.col.f32.tf32.tf32.f32 "
        "{%0,%1,%2,%3}, {%4,%5,%6,%7}, {%8,%9}, {%0,%1,%2,%3};"
        : "+f"(c[0]), "+f"(c[1]), "+f"(c[2]), "+f"(c[3])
        : "r"(a[0]), "r"(a[1]), "r"(a[2]), "r"(a[3]), "r"(b[0]), "r"(b[1]));
}

// ---------------------------------------------------------------------------
// Embedding
// ---------------------------------------------------------------------------
__global__ void embed_kernel(const int* __restrict__ tokens,
                             const float* __restrict__ tok_emb,
                             const float* __restrict__ pos_emb) {
    int idx = blockIdx.x * blockDim.x + threadIdx.x;
    if (idx >= MROWS * Dm / 4) return;
    int row = idx / (Dm / 4);
    int c4  = idx % (Dm / 4);
    int s   = row % Sq;
    int tok = tokens[row];
    float4 te = reinterpret_cast<const float4*>(tok_emb + (size_t)tok * Dm)[c4];
    float4 pe = reinterpret_cast<const float4*>(pos_emb + (size_t)s * Dm)[c4];
    te.x += pe.x; te.y += pe.y; te.z += pe.z; te.w += pe.w;
    reinterpret_cast<float4*>(g_x)[idx] = te;
}

// ---------------------------------------------------------------------------
// LayerNorm
// ---------------------------------------------------------------------------
__global__ __launch_bounds__(256) void ln_kernel(const float* __restrict__ x,
                                                 const float* __restrict__ gw,
                                                 const float* __restrict__ bw,
                                                 float* __restrict__ out) {
    int row = blockIdx.x;
    int tid = threadIdx.x;
    const float* xr = x + (size_t)row * Dm;

    float v[4];
    float s = 0.f, s2 = 0.f;
#pragma unroll
    for (int i = 0; i < 4; i++) {
        v[i] = xr[tid + i * 256];
        s += v[i];
        s2 += v[i] * v[i];
    }
#pragma unroll
    for (int o = 16; o > 0; o >>= 1) {
        s  += __shfl_xor_sync(0xffffffffu, s,  o);
        s2 += __shfl_xor_sync(0xffffffffu, s2, o);
    }
    __shared__ float ws[8], ws2[8];
    int w = tid >> 5, l = tid & 31;
    if (l == 0) { ws[w] = s; ws2[w] = s2; }
    __syncthreads();
    s = 0.f; s2 = 0.f;
#pragma unroll
    for (int i = 0; i < 8; i++) { s += ws[i]; s2 += ws2[i]; }
    float mean = s * (1.0f / Dm);
    float var  = s2 * (1.0f / Dm) - mean * mean;
    float rstd = rsqrtf(var + 1e-5f);

    float* orow = out + (size_t)row * Dm;
#pragma unroll
    for (int i = 0; i < 4; i++) {
        int col = tid + i * 256;
        orow[col] = (v[i] - mean) * rstd * gw[col] + bw[col];
    }
}

// ---------------------------------------------------------------------------
// TF32 tensor-core GEMM: C[M,N] = A[M,K] @ B ; B is [K,N] (or [N,K] if TB)
// Block 128x128, BK=16, 256 threads (8 warps, 2x4), warp tile 64x32.
// Epilogue OP: 0 none, 1 +res, 2 gelu(acc+bias), 3 res+acc+bias
// smem: A as [128][20] (stride-20 pad), B as [16][132] (non-TB) or [128][20] (TB)
// ---------------------------------------------------------------------------
#define ASTRIDE 20
#define BSTRIDE 132

template <int OP, bool TB>
__device__ __forceinline__ void gemm_mma_body(const float* __restrict__ A,
                                              const float* __restrict__ Bm,
                                              const float* __restrict__ bias,
                                              const float* __restrict__ res,
                                              float* __restrict__ C,
                                              int M, int N, int K,
                                              int m0, int n0) {
    __shared__ float sA[2][128 * ASTRIDE];
    __shared__ float sB[2][2560];   // max(16*132, 128*20)

    int tid = threadIdx.x;
    int warp = tid >> 5;
    int lane = tid & 31;
    int g  = lane >> 2;   // group 0..7
    int tg = lane & 3;    // 0..3
    int wm = warp & 1;    // 0..1 -> 64 M rows each
    int wn = warp >> 1;   // 0..3 -> 32 N cols each

    float acc[4][4][4];
#pragma unroll
    for (int mt = 0; mt < 4; mt++)
#pragma unroll
        for (int nt = 0; nt < 4; nt++)
#pragma unroll
            for (int i = 0; i < 4; i++) acc[mt][nt][i] = 0.f;

    // ---- load indices ----
    // A tile: 128 rows x 16 k. 512 float4 slots: id -> m=id/4, kc=id%4
    int a_m  = tid >> 1;            // with 2 passes: slots tid + p*256
    // B (non-TB): 16 rows x 128 cols: 512 slots: id -> k=id/32, n4=id%32
    // B (TB): 128 rows x 4 chunks: id -> n=id/4, kc=id%4

    int KT = K / 16;

    // prologue: stage 0
    {
        int k0 = 0;
#pragma unroll
        for (int p = 0; p < 2; p++) {
            int id = tid + p * 256;
            int m = id >> 2, kc = id & 3;
            cpasync16(&sA[0][m * ASTRIDE + kc * 4],
                      A + (size_t)(m0 + m) * K + k0 + kc * 4);
        }
        if (!TB) {
#pragma unroll
            for (int p = 0; p < 2; p++) {
                int id = tid + p * 256;
                int k = id >> 5, n4 = id & 31;
                cpasync16(&sB[0][k * BSTRIDE + n4 * 4],
                          Bm + (size_t)(k0 + k) * N + n0 + n4 * 4);
            }
        } else {
#pragma unroll
            for (int p = 0; p < 2; p++) {
                int id = tid + p * 256;
                int n = id >> 2, kc = id & 3;
                int nn = n0 + n; if (nn > N - 1) nn = N - 1;
                cpasync16(&sB[0][n * ASTRIDE + kc * 4],
                          Bm + (size_t)nn * K + k0 + kc * 4);
            }
        }
        CP_COMMIT();
    }

    int stage = 0;
    for (int kt = 0; kt < KT; kt++) {
        if (kt + 1 < KT) {
            int k0 = (kt + 1) * 16;
            int ns = stage ^ 1;
#pragma unroll
            for (int p = 0; p < 2; p++) {
                int id = tid + p * 256;
                int m = id >> 2, kc = id & 3;
                cpasync16(&sA[ns][m * ASTRIDE + kc * 4],
                          A + (size_t)(m0 + m) * K + k0 + kc * 4);
            }
            if (!TB) {
#pragma unroll
                for (int p = 0; p < 2; p++) {
                    int id = tid + p * 256;
                    int k = id >> 5, n4 = id & 31;
                    cpasync16(&sB[ns][k * BSTRIDE + n4 * 4],
                              Bm + (size_t)(k0 + k) * N + n0 + n4 * 4);
                }
            } else {
#pragma unroll
                for (int p = 0; p < 2; p++) {
                    int id = tid + p * 256;
                    int n = id >> 2, kc = id & 3;
                    int nn = n0 + n; if (nn > N - 1) nn = N - 1;
                    cpasync16(&sB[ns][n * ASTRIDE + kc * 4],
                              Bm + (size_t)nn * K + k0 + kc * 4);
                }
            }
            CP_COMMIT();
            CP_WAIT1();
        } else {
            CP_WAIT0();
        }
        __syncthreads();

        const float* As = sA[stage];
        const float* Bs = sB[stage];

#pragma unroll
        for (int kk = 0; kk < 2; kk++) {
            int kb = kk * 8;
            uint32_t afr[4][4];
#pragma unroll
            for (int mt = 0; mt < 4; mt++) {
                int rowb = wm * 64 + mt * 16;
                afr[mt][0] = f2tf(As[(rowb + g) * ASTRIDE + kb + tg]);
                afr[mt][1] = f2tf(As[(rowb + g + 8) * ASTRIDE + kb + tg]);
                afr[mt][2] = f2tf(As[(rowb + g) * ASTRIDE + kb + tg + 4]);
                afr[mt][3] = f2tf(As[(rowb + g + 8) * ASTRIDE + kb + tg + 4]);
            }
            uint32_t bfr[4][2];
#pragma unroll
            for (int nt = 0; nt < 4; nt++) {
                int col = wn * 32 + nt * 8 + g;
                if (!TB) {
                    bfr[nt][0] = f2tf(Bs[(kb + tg) * BSTRIDE + col]);
                    bfr[nt][1] = f2tf(Bs[(kb + tg + 4) * BSTRIDE + col]);
                } else {
                    bfr[nt][0] = f2tf(Bs[col * ASTRIDE + kb + tg]);
                    bfr[nt][1] = f2tf(Bs[col * ASTRIDE + kb + tg + 4]);
                }
            }
#pragma unroll
            for (int mt = 0; mt < 4; mt++)
#pragma unroll
                for (int nt = 0; nt < 4; nt++)
                    mma_tf32(acc[mt][nt], afr[mt], bfr[nt]);
        }
        __syncthreads();
        stage ^= 1;
    }

    // ---- epilogue ----
#pragma unroll
    for (int mt = 0; mt < 4; mt++) {
#pragma unroll
        for (int half = 0; half < 2; half++) {
            int m = m0 + wm * 64 + mt * 16 + g + half * 8;
#pragma unroll
            for (int nt = 0; nt < 4; nt++) {
                int col = n0 + wn * 32 + nt * 8 + tg * 2;
                float v0 = acc[mt][nt][half * 2 + 0];
                float v1 = acc[mt][nt][half * 2 + 1];
                if (OP == 2 || OP == 3) {
                    // guard bias index when TB tail (TB is OP0 in practice)
                    v0 += bias[col];
                    v1 += bias[col + 1];
                }
                if (OP == 2) {
                    v0 = 0.5f * v0 * (1.0f + erff(v0 * 0.70710678118654752f));
                    v1 = 0.5f * v1 * (1.0f + erff(v1 * 0.70710678118654752f));
                }
                if (OP == 1 || OP == 3) {
                    float2 r = *reinterpret_cast<const float2*>(res + (size_t)m * N + col);
                    v0 += r.x; v1 += r.y;
                }
                if (TB) {
                    if (col < N)     C[(size_t)m * N + col]     = v0;
                    if (col + 1 < N) C[(size_t)m * N + col + 1] = v1;
                } else {
                    float2 o; o.x = v0; o.y = v1;
                    *reinterpret_cast<float2*>(C + (size_t)m * N + col) = o;
                }
            }
        }
    }
}

template <int OP, bool TB>
__global__ __launch_bounds__(256) void gemm_mma_kernel(const float* __restrict__ A,
                                                       const float* __restrict__ Bm,
                                                       const float* __restrict__ bias,
                                                       const float* __restrict__ res,
                                                       float* __restrict__ C,
                                                       int M, int N, int K) {
    gemm_mma_body<OP, TB>(A, Bm, bias, res, C, M, N, K,
                          blockIdx.y * 128, blockIdx.x * 128);
}

__global__ __launch_bounds__(256) void qkv_mma_kernel(const float* __restrict__ A,
                                                      const float* __restrict__ Wq,
                                                      const float* __restrict__ Wk,
                                                      const float* __restrict__ Wv,
                                                      float* __restrict__ Qo,
                                                      float* __restrict__ Ko,
                                                      float* __restrict__ Vo) {
    const float* Bm = (blockIdx.z == 0) ? Wq : (blockIdx.z == 1 ? Wk : Wv);
    float* C = (blockIdx.z == 0) ? Qo : (blockIdx.z == 1 ? Ko : Vo);
    gemm_mma_body<0, false>(A, Bm, nullptr, nullptr, C, MROWS, Dm, Dm,
                            blockIdx.y * 128, blockIdx.x * 128);
}

// ---------------------------------------------------------------------------
// Flash attention (fp32 SIMT, unchanged)
// ---------------------------------------------------------------------------
__global__ __launch_bounds__(256) void attn_kernel(const float* __restrict__ Qg,
                                                   const float* __restrict__ Kg,
                                                   const float* __restrict__ Vg,
                                                   float* __restrict__ Og) {
    __shared__ float Qs[64][64];
    __shared__ float Ks[64][64];
    __shared__ float Vs[64][64];

    int b = blockIdx.z, h = blockIdx.y, qi = blockIdx.x;
    int tid = threadIdx.x;

    for (int t = tid; t < 1024; t += 256) {
        int r = t >> 4, c4 = t & 15;
        float4 v = *reinterpret_cast<const float4*>(
            Qg + ((size_t)(b * Sq + qi * 64 + r) * Dm) + h * HDm + c4 * 4);
        *reinterpret_cast<float4*>(&Qs[r][c4 * 4]) = v;
    }

    int q = tid >> 2, c = tid & 3;
    float m_i = -INFINITY;
    float l_i = 0.f;
    float o[16];
#pragma unroll
    for (int d = 0; d < 16; d++) o[d] = 0.f;
    const float scale = 0.125f;
    int qg = qi * 64 + q;

    for (int j = 0; j <= qi; j++) {
        __syncthreads();
        for (int t = tid; t < 1024; t += 256) {
            int r = t >> 4, c4 = t & 15;
            size_t base = ((size_t)(b * Sq + j * 64 + r) * Dm) + h * HDm + c4 * 4;
            *reinterpret_cast<float4*>(&Ks[r][c4 * 4]) =
                *reinterpret_cast<const float4*>(Kg + base);
            *reinterpret_cast<float4*>(&Vs[r][c4 * 4]) =
                *reinterpret_cast<const float4*>(Vg + base);
        }
        __syncthreads();

        float s[16];
#pragma unroll
        for (int kk = 0; kk < 16; kk++) s[kk] = 0.f;
#pragma unroll 4
        for (int kd4 = 0; kd4 < 16; kd4++) {
            float4 qv = *reinterpret_cast<const float4*>(&Qs[q][kd4 * 4]);
#pragma unroll
            for (int kk = 0; kk < 16; kk++) {
                float4 kv = *reinterpret_cast<const float4*>(&Ks[c * 16 + kk][kd4 * 4]);
                s[kk] += qv.x * kv.x + qv.y * kv.y + qv.z * kv.z + qv.w * kv.w;
            }
        }
#pragma unroll
        for (int kk = 0; kk < 16; kk++) {
            int kg = j * 64 + c * 16 + kk;
            s[kk] = (kg <= qg) ? s[kk] * scale : -INFINITY;
        }
        float mloc = s[0];
#pragma unroll
        for (int kk = 1; kk < 16; kk++) mloc = fmaxf(mloc, s[kk]);
        mloc = fmaxf(mloc, __shfl_xor_sync(0xffffffffu, mloc, 1, 4));
        mloc = fmaxf(mloc, __shfl_xor_sync(0xffffffffu, mloc, 2, 4));
        float mnew = fmaxf(m_i, mloc);
        float alpha = expf(m_i - mnew);

        float p[16];
        float lloc = 0.f;
#pragma unroll
        for (int kk = 0; kk < 16; kk++) {
            p[kk] = expf(s[kk] - mnew);
            lloc += p[kk];
        }
        lloc += __shfl_xor_sync(0xffffffffu, lloc, 1, 4);
        lloc += __shfl_xor_sync(0xffffffffu, lloc, 2, 4);
        l_i = l_i * alpha + lloc;
        m_i = mnew;
#pragma unroll
        for (int d = 0; d < 16; d++) o[d] *= alpha;

#pragma unroll
        for (int src = 0; src < 4; src++) {
#pragma unroll
            for (int kk = 0; kk < 16; kk++) {
                float pv = __shfl_sync(0xffffffffu, p[kk], src, 4);
                int key = src * 16 + kk;
#pragma unroll
                for (int d4 = 0; d4 < 4; d4++) {
                    float4 vv = *reinterpret_cast<const float4*>(&Vs[key][c * 16 + d4 * 4]);
                    o[d4 * 4 + 0] += pv * vv.x;
                    o[d4 * 4 + 1] += pv * vv.y;
                    o[d4 * 4 + 2] += pv * vv.z;
                    o[d4 * 4 + 3] += pv * vv.w;
                }
            }
        }
    }

    float inv = 1.0f / l_i;
    size_t obase = ((size_t)(b * Sq + qi * 64 + q) * Dm) + h * HDm + c * 16;
#pragma unroll
    for (int d4 = 0; d4 < 4; d4++) {
        float4 ov;
        ov.x = o[d4 * 4 + 0] * inv;
        ov.y = o[d4 * 4 + 1] * inv;
        ov.z = o[d4 * 4 + 2] * inv;
        ov.w = o[d4 * 4 + 3] * inv;
        *reinterpret_cast<float4*>(Og + obase + d4 * 4) = ov;
    }
}

// ---------------------------------------------------------------------------
// Host launch
// ---------------------------------------------------------------------------
extern "C" void kernel_launch(void* const* d_in, const int* in_sizes, int n_in,
                              void* d_out, int out_size) {
    const int*   tokens  = (const int*)d_in[0];
    const float* tok_emb = (const float*)d_in[1];
    const float* pos_emb = (const float*)d_in[2];
    const float* ln1_g   = (const float*)d_in[3];
    const float* ln1_b   = (const float*)d_in[4];
    const float* wq      = (const float*)d_in[5];
    const float* wk      = (const float*)d_in[6];
    const float* wv      = (const float*)d_in[7];
    const float* wo      = (const float*)d_in[8];
    const float* ln2_g   = (const float*)d_in[9];
    const float* ln2_b   = (const float*)d_in[10];
    const float* w1      = (const float*)d_in[11];
    const float* b1      = (const float*)d_in[12];
    const float* w2      = (const float*)d_in[13];
    const float* b2      = (const float*)d_in[14];
    const float* lnf_g   = (const float*)d_in[15];
    const float* lnf_b   = (const float*)d_in[16];
    float* out = (float*)d_out;

    float *px, *ph, *pq, *pk, *pv, *pa, *pf;
    cudaGetSymbolAddress((void**)&px, g_x);
    cudaGetSymbolAddress((void**)&ph, g_h);
    cudaGetSymbolAddress((void**)&pq, g_q);
    cudaGetSymbolAddress((void**)&pk, g_k);
    cudaGetSymbolAddress((void**)&pv, g_v);
    cudaGetSymbolAddress((void**)&pa, g_att);
    cudaGetSymbolAddress((void**)&pf, g_ff);

    embed_kernel<<<MROWS * Dm / 4 / 256, 256>>>(tokens, tok_emb, pos_emb);

    dim3 gD(Dm / 128, MROWS / 128);        // (8,16)
    dim3 gQKV(Dm / 128, MROWS / 128, 3);
    dim3 gFF(FFd / 128, MROWS / 128);      // (32,16)
    dim3 gAttn(Sq / 64, Hh, Bz);

    for (int l = 0; l < Ll; l++) {
        const float* lWq = wq + (size_t)l * Dm * Dm;
        const float* lWk = wk + (size_t)l * Dm * Dm;
        const float* lWv = wv + (size_t)l * Dm * Dm;
        const float* lWo = wo + (size_t)l * Dm * Dm;
        const float* lW1 = w1 + (size_t)l * Dm * FFd;
        const float* lB1 = b1 + (size_t)l * FFd;
        const float* lW2 = w2 + (size_t)l * FFd * Dm;
        const float* lB2 = b2 + (size_t)l * Dm;

        ln_kernel<<<MROWS, 256>>>(px, ln1_g + (size_t)l * Dm, ln1_b + (size_t)l * Dm, ph);
        qkv_mma_kernel<<<gQKV, 256>>>(ph, lWq, lWk, lWv, pq, pk, pv);
        attn_kernel<<<gAttn, 256>>>(pq, pk, pv, pa);
        gemm_mma_kernel<1, false><<<gD, 256>>>(pa, lWo, nullptr, px, px, MROWS, Dm, Dm);
        ln_kernel<<<MROWS, 256>>>(px, ln2_g + (size_t)l * Dm, ln2_b + (size_t)l * Dm, ph);
        gemm_mma_kernel<2, false><<<gFF, 256>>>(ph, lW1, lB1, nullptr, pf, MROWS, FFd, Dm);
        gemm_mma_kernel<3, false><<<gD, 256>>>(pf, lW2, lB2, px, px, MROWS, Dm, FFd);
    }

    ln_kernel<<<MROWS, 256>>>(px, lnf_g, lnf_b, ph);
    dim3 gLog((Vv + 127) / 128, MROWS / 128);  // (393,16)
    gemm_mma_kernel<0, true><<<gLog, 256>>>(ph, tok_emb, nullptr, nullptr, out,
                                            MROWS, Vv, Dm);
}

// round 7
// speedup vs baseline: 1.0255x; 1.0255x over previous
#include <cuda_runtime.h>
#include <math.h>
#include <stdint.h>

#define Bz 2
#define Sq 1024
#define Dm 1024
#define Hh 16
#define Ll 6
#define Vv 50257
#define HDm 64
#define MROWS (Bz * Sq)
#define FFd (4 * Dm)

__device__ float g_x[MROWS * Dm];
__device__ float g_h[MROWS * Dm];
__device__ float g_q[MROWS * Dm];
__device__ float g_k[MROWS * Dm];
__device__ float g_v[MROWS * Dm];
__device__ float g_att[MROWS * Dm];
__device__ float g_ff[MROWS * FFd];
__device__ float g_wqt[Ll * Dm * Dm];
__device__ float g_wkt[Ll * Dm * Dm];
__device__ float g_wvt[Ll * Dm * Dm];
__device__ float g_wot[Ll * Dm * Dm];
__device__ float g_w1t[(size_t)Ll * Dm * FFd];
__device__ float g_w2t[(size_t)Ll * FFd * Dm];
__device__ float g_embr[(size_t)Vv * Dm];

__device__ __forceinline__ float rnaf(float x) {
    uint32_t u;
    asm("cvt.rna.tf32.f32 %0, %1;" : "=r"(u) : "f"(x));
    return __uint_as_float(u);
}
__device__ __forceinline__ void cpasync16(void* sdst, const void* gsrc) {
    uint32_t d = (uint32_t)__cvta_generic_to_shared(sdst);
    asm volatile("cp.async.cg.shared.global [%0], [%1], 16;" :: "r"(d), "l"(gsrc));
}
__device__ __forceinline__ void mma_tf32(float* c, const uint32_t* a, const uint32_t* b) {
    asm volatile(
        "mma.sync.aligned.m16n8k8.row.col.f32.tf32.tf32.f32 "
        "{%0,%1,%2,%3}, {%4,%5,%6,%7}, {%8,%9}, {%0,%1,%2,%3};"
        : "+f"(c[0]), "+f"(c[1]), "+f"(c[2]), "+f"(c[3])
        : "r"(a[0]), "r"(a[1]), "r"(a[2]), "r"(a[3]), "r"(b[0]), "r"(b[1]));
}

// ---------------------------------------------------------------------------
__global__ void embed_kernel(const int* __restrict__ tokens,
                             const float* __restrict__ tok_emb,
                             const float* __restrict__ pos_emb) {
    int idx = blockIdx.x * blockDim.x + threadIdx.x;
    if (idx >= MROWS * Dm / 4) return;
    int row = idx / (Dm / 4), c4 = idx % (Dm / 4), s = row % Sq;
    int tok = tokens[row];
    float4 te = reinterpret_cast<const float4*>(tok_emb + (size_t)tok * Dm)[c4];
    float4 pe = reinterpret_cast<const float4*>(pos_emb + (size_t)s * Dm)[c4];
    te.x += pe.x; te.y += pe.y; te.z += pe.z; te.w += pe.w;
    reinterpret_cast<float4*>(g_x)[idx] = te;
}

__global__ __launch_bounds__(256) void transpose_rna_kernel(const float* __restrict__ W,
                                                            float* __restrict__ WT, int K, int N) {
    __shared__ float t[32][33];
    const float* Wl = W + (size_t)blockIdx.z * K * N;
    float* WTl = WT + (size_t)blockIdx.z * K * N;
    int n0 = blockIdx.x * 32, k0 = blockIdx.y * 32;
    int tx = threadIdx.x & 31, ty = threadIdx.x >> 5;
#pragma unroll
    for (int i = 0; i < 32; i += 8)
        t[ty + i][tx] = Wl[(size_t)(k0 + ty + i) * N + n0 + tx];
    __syncthreads();
#pragma unroll
    for (int i = 0; i < 32; i += 8)
        WTl[(size_t)(n0 + ty + i) * K + k0 + tx] = rnaf(t[tx][ty + i]);
}

__global__ __launch_bounds__(256) void round_emb_kernel(const float* __restrict__ E, float* __restrict__ O) {
    size_t base = (size_t)blockIdx.x * Dm + threadIdx.x * 4;
    float4 v = *reinterpret_cast<const float4*>(E + base);
    v.x = rnaf(v.x); v.y = rnaf(v.y); v.z = rnaf(v.z); v.w = rnaf(v.w);
    *reinterpret_cast<float4*>(O + base) = v;
}

__global__ __launch_bounds__(256) void ln_kernel(const float* __restrict__ x,
                                                 const float* __restrict__ gw,
                                                 const float* __restrict__ bw,
                                                 float* __restrict__ out) {
    int row = blockIdx.x, tid = threadIdx.x;
    const float* xr = x + (size_t)row * Dm;
    float v[4], s = 0.f, s2 = 0.f;
#pragma unroll
    for (int i = 0; i < 4; i++) { v[i] = xr[tid + i * 256]; s += v[i]; s2 += v[i] * v[i]; }
#pragma unroll
    for (int o = 16; o > 0; o >>= 1) {
        s += __shfl_xor_sync(0xffffffffu, s, o);
        s2 += __shfl_xor_sync(0xffffffffu, s2, o);
    }
    __shared__ float ws[8], ws2[8];
    int w = tid >> 5, l = tid & 31;
    if (l == 0) { ws[w] = s; ws2[w] = s2; }
    __syncthreads();
    s = 0.f; s2 = 0.f;
#pragma unroll
    for (int i = 0; i < 8; i++) { s += ws[i]; s2 += ws2[i]; }
    float mean = s * (1.0f / Dm);
    float var = s2 * (1.0f / Dm) - mean * mean;
    float rstd = rsqrtf(var + 1e-5f);
    float* orow = out + (size_t)row * Dm;
#pragma unroll
    for (int i = 0; i < 4; i++) {
        int col = tid + i * 256;
        orow[col] = rnaf((v[i] - mean) * rstd * gw[col] + bw[col]);
    }
}

// ---------------------------------------------------------------------------
// TF32 mma.sync GEMM: C[M,N] = A[M,K] @ Bt[N,K]^T.  Inputs pre-rounded to tf32.
// CTA 128x128, BK=32, 3-stage cp.async, 256 threads (8 warps 2x4), warp 64x32.
// smem rows stride 36 words (conflict-free frag loads).
// VEC (template): N is even -> float2 stores are aligned. Odd N (logits) -> scalar.
// OP: 0 none, 1 +res, 2 rna(gelu(acc+bias)), 3 acc+bias+res
// ---------------------------------------------------------------------------
#define RSTRIDE 36
#define STAGE_BYTES (2 * 128 * RSTRIDE * 4)   // 36864
#define SMEM_TOTAL (3 * STAGE_BYTES)          // 110592

template <int OP, bool VEC>
__device__ __forceinline__ void gemm_body(const float* __restrict__ A, const float* __restrict__ Bt,
                                          const float* __restrict__ bias, const float* __restrict__ res,
                                          float* __restrict__ C, int M, int N, int K,
                                          int m0, int n0) {
    extern __shared__ char smem[];
    int tid = threadIdx.x, warp = tid >> 5, lane = tid & 31;
    int g = lane >> 2, tg = lane & 3;
    int wm = warp & 1, wn = warp >> 1;

    float acc[4][4][4];
#pragma unroll
    for (int mt = 0; mt < 4; mt++)
#pragma unroll
        for (int nt = 0; nt < 4; nt++)
#pragma unroll
            for (int i = 0; i < 4; i++) acc[mt][nt][i] = 0.f;

    const int KT = K / 32;

    auto loadStage = [&](int stg) {
        char* base = smem + (stg % 3) * STAGE_BYTES;
        char* sa = base;
        char* sbf = base + 128 * RSTRIDE * 4;
        const float* Ak = A + (size_t)m0 * K + stg * 32;
        const float* Bk = Bt + stg * 32;
#pragma unroll
        for (int p = 0; p < 4; p++) {
            int id = tid + p * 256, r = id >> 3, c = id & 7;
            cpasync16(sa + r * (RSTRIDE * 4) + c * 16, Ak + (size_t)r * K + c * 4);
        }
#pragma unroll
        for (int p = 0; p < 4; p++) {
            int id = tid + p * 256, r = id >> 3, c = id & 7;
            int n = n0 + r; if (n >= N) n = N - 1;
            cpasync16(sbf + r * (RSTRIDE * 4) + c * 16, Bk + (size_t)n * K + c * 4);
        }
        asm volatile("cp.async.commit_group;");
    };

    loadStage(0);
    loadStage(1);

    for (int j = 0; j < KT; j++) {
        if (j + 1 < KT) asm volatile("cp.async.wait_group 1;");
        else            asm volatile("cp.async.wait_group 0;");
        __syncthreads();
        if (j + 2 < KT) loadStage(j + 2);

        const uint32_t* As = reinterpret_cast<const uint32_t*>(smem + (j % 3) * STAGE_BYTES);
        const uint32_t* Bs = As + 128 * RSTRIDE;

#pragma unroll
        for (int kk = 0; kk < 4; kk++) {
            int kb = kk * 8;
            uint32_t afr[4][4];
#pragma unroll
            for (int mt = 0; mt < 4; mt++) {
                int r0 = (wm * 64 + mt * 16 + g) * RSTRIDE;
                afr[mt][0] = As[r0 + kb + tg];
                afr[mt][1] = As[r0 + 8 * RSTRIDE + kb + tg];
                afr[mt][2] = As[r0 + kb + tg + 4];
                afr[mt][3] = As[r0 + 8 * RSTRIDE + kb + tg + 4];
            }
            uint32_t bfr[4][2];
#pragma unroll
            for (int nt = 0; nt < 4; nt++) {
                int rb = (wn * 32 + nt * 8 + g) * RSTRIDE;
                bfr[nt][0] = Bs[rb + kb + tg];
                bfr[nt][1] = Bs[rb + kb + tg + 4];
            }
#pragma unroll
            for (int mt = 0; mt < 4; mt++)
#pragma unroll
                for (int nt = 0; nt < 4; nt++)
                    mma_tf32(acc[mt][nt], afr[mt], bfr[nt]);
        }
    }

#pragma unroll
    for (int mt = 0; mt < 4; mt++) {
#pragma unroll
        for (int half = 0; half < 2; half++) {
            int m = m0 + wm * 64 + mt * 16 + g + half * 8;
#pragma unroll
            for (int nt = 0; nt < 4; nt++) {
                int col = n0 + wn * 32 + nt * 8 + tg * 2;
                float v0 = acc[mt][nt][half * 2 + 0];
                float v1 = acc[mt][nt][half * 2 + 1];
                if (OP == 2 || OP == 3) { v0 += bias[col]; v1 += bias[col + 1]; }
                if (OP == 2) {
                    v0 = rnaf(0.5f * v0 * (1.0f + erff(v0 * 0.70710678118654752f)));
                    v1 = rnaf(0.5f * v1 * (1.0f + erff(v1 * 0.70710678118654752f)));
                }
                if (OP == 1 || OP == 3) {
                    float2 r = *reinterpret_cast<const float2*>(res + (size_t)m * N + col);
                    v0 += r.x; v1 += r.y;
                }
                if (VEC) {
                    // N even and tile fully interior: m*N+col is even -> aligned
                    float2 o; o.x = v0; o.y = v1;
                    *reinterpret_cast<float2*>(C + (size_t)m * N + col) = o;
                } else {
                    if (col < N)     C[(size_t)m * N + col]     = v0;
                    if (col + 1 < N) C[(size_t)m * N + col + 1] = v1;
                }
            }
        }
    }
}

template <int OP, bool VEC>
__global__ __launch_bounds__(256) void gemm_kernel(const float* __restrict__ A, const float* __restrict__ Bt,
                                                   const float* __restrict__ bias, const float* __restrict__ res,
                                                   float* __restrict__ C, int M, int N, int K) {
    gemm_body<OP, VEC>(A, Bt, bias, res, C, M, N, K, blockIdx.y * 128, blockIdx.x * 128);
}

__global__ __launch_bounds__(256) void qkv_kernel(const float* __restrict__ A, const float* __restrict__ Wqt,
                                                  const float* __restrict__ Wkt, const float* __restrict__ Wvt,
                                                  float* __restrict__ Qo, float* __restrict__ Ko,
                                                  float* __restrict__ Vo) {
    const float* Bt = (blockIdx.z == 0) ? Wqt : (blockIdx.z == 1 ? Wkt : Wvt);
    float* C = (blockIdx.z == 0) ? Qo : (blockIdx.z == 1 ? Ko : Vo);
    gemm_body<0, true>(A, Bt, nullptr, nullptr, C, MROWS, Dm, Dm, blockIdx.y * 128, blockIdx.x * 128);
}

// ---------------------------------------------------------------------------
__global__ __launch_bounds__(256) void attn_kernel(const float* __restrict__ Qg,
                                                   const float* __restrict__ Kg,
                                                   const float* __restrict__ Vg,
                                                   float* __restrict__ Og) {
    __shared__ float Qs[64][64];
    __shared__ float Ks[64][64];
    __shared__ float Vs[64][64];
    int b = blockIdx.z, h = blockIdx.y, qi = blockIdx.x;
    int tid = threadIdx.x;
    for (int t = tid; t < 1024; t += 256) {
        int r = t >> 4, c4 = t & 15;
        float4 v = *reinterpret_cast<const float4*>(
            Qg + ((size_t)(b * Sq + qi * 64 + r) * Dm) + h * HDm + c4 * 4);
        *reinterpret_cast<float4*>(&Qs[r][c4 * 4]) = v;
    }
    int q = tid >> 2, c = tid & 3;
    float m_i = -INFINITY, l_i = 0.f;
    float o[16];
#pragma unroll
    for (int d = 0; d < 16; d++) o[d] = 0.f;
    const float scale = 0.125f;
    int qg = qi * 64 + q;

    for (int j = 0; j <= qi; j++) {
        __syncthreads();
        for (int t = tid; t < 1024; t += 256) {
            int r = t >> 4, c4 = t & 15;
            size_t base = ((size_t)(b * Sq + j * 64 + r) * Dm) + h * HDm + c4 * 4;
            *reinterpret_cast<float4*>(&Ks[r][c4 * 4]) = *reinterpret_cast<const float4*>(Kg + base);
            *reinterpret_cast<float4*>(&Vs[r][c4 * 4]) = *reinterpret_cast<const float4*>(Vg + base);
        }
        __syncthreads();
        float s[16];
#pragma unroll
        for (int kk = 0; kk < 16; kk++) s[kk] = 0.f;
#pragma unroll 4
        for (int kd4 = 0; kd4 < 16; kd4++) {
            float4 qv = *reinterpret_cast<const float4*>(&Qs[q][kd4 * 4]);
#pragma unroll
            for (int kk = 0; kk < 16; kk++) {
                float4 kv = *reinterpret_cast<const float4*>(&Ks[c * 16 + kk][kd4 * 4]);
                s[kk] += qv.x * kv.x + qv.y * kv.y + qv.z * kv.z + qv.w * kv.w;
            }
        }
#pragma unroll
        for (int kk = 0; kk < 16; kk++) {
            int kg = j * 64 + c * 16 + kk;
            s[kk] = (kg <= qg) ? s[kk] * scale : -INFINITY;
        }
        float mloc = s[0];
#pragma unroll
        for (int kk = 1; kk < 16; kk++) mloc = fmaxf(mloc, s[kk]);
        mloc = fmaxf(mloc, __shfl_xor_sync(0xffffffffu, mloc, 1, 4));
        mloc = fmaxf(mloc, __shfl_xor_sync(0xffffffffu, mloc, 2, 4));
        float mnew = fmaxf(m_i, mloc);
        float alpha = expf(m_i - mnew);
        float p[16], lloc = 0.f;
#pragma unroll
        for (int kk = 0; kk < 16; kk++) { p[kk] = expf(s[kk] - mnew); lloc += p[kk]; }
        lloc += __shfl_xor_sync(0xffffffffu, lloc, 1, 4);
        lloc += __shfl_xor_sync(0xffffffffu, lloc, 2, 4);
        l_i = l_i * alpha + lloc;
        m_i = mnew;
#pragma unroll
        for (int d = 0; d < 16; d++) o[d] *= alpha;
#pragma unroll
        for (int src = 0; src < 4; src++) {
#pragma unroll
            for (int kk = 0; kk < 16; kk++) {
                float pv = __shfl_sync(0xffffffffu, p[kk], src, 4);
                int key = src * 16 + kk;
#pragma unroll
                for (int d4 = 0; d4 < 4; d4++) {
                    float4 vv = *reinterpret_cast<const float4*>(&Vs[key][c * 16 + d4 * 4]);
                    o[d4 * 4 + 0] += pv * vv.x;
                    o[d4 * 4 + 1] += pv * vv.y;
                    o[d4 * 4 + 2] += pv * vv.z;
                    o[d4 * 4 + 3] += pv * vv.w;
                }
            }
        }
    }
    float inv = 1.0f / l_i;
    size_t obase = ((size_t)(b * Sq + qi * 64 + q) * Dm) + h * HDm + c * 16;
#pragma unroll
    for (int d4 = 0; d4 < 4; d4++) {
        float4 ov;
        ov.x = rnaf(o[d4 * 4 + 0] * inv);
        ov.y = rnaf(o[d4 * 4 + 1] * inv);
        ov.z = rnaf(o[d4 * 4 + 2] * inv);
        ov.w = rnaf(o[d4 * 4 + 3] * inv);
        *reinterpret_cast<float4*>(Og + obase + d4 * 4) = ov;
    }
}

// ---------------------------------------------------------------------------
extern "C" void kernel_launch(void* const* d_in, const int* in_sizes, int n_in,
                              void* d_out, int out_size) {
    const int*   tokens  = (const int*)d_in[0];
    const float* tok_emb = (const float*)d_in[1];
    const float* pos_emb = (const float*)d_in[2];
    const float* ln1_g = (const float*)d_in[3];
    const float* ln1_b = (const float*)d_in[4];
    const float* wq = (const float*)d_in[5];
    const float* wk = (const float*)d_in[6];
    const float* wv = (const float*)d_in[7];
    const float* wo = (const float*)d_in[8];
    const float* ln2_g = (const float*)d_in[9];
    const float* ln2_b = (const float*)d_in[10];
    const float* w1 = (const float*)d_in[11];
    const float* b1 = (const float*)d_in[12];
    const float* w2 = (const float*)d_in[13];
    const float* b2 = (const float*)d_in[14];
    const float* lnf_g = (const float*)d_in[15];
    const float* lnf_b = (const float*)d_in[16];
    float* out = (float*)d_out;

    float *px, *ph, *pq, *pk, *pv, *pa, *pf, *pwqt, *pwkt, *pwvt, *pwot, *pw1t, *pw2t, *pembr;
    cudaGetSymbolAddress((void**)&px, g_x);
    cudaGetSymbolAddress((void**)&ph, g_h);
    cudaGetSymbolAddress((void**)&pq, g_q);
    cudaGetSymbolAddress((void**)&pk, g_k);
    cudaGetSymbolAddress((void**)&pv, g_v);
    cudaGetSymbolAddress((void**)&pa, g_att);
    cudaGetSymbolAddress((void**)&pf, g_ff);
    cudaGetSymbolAddress((void**)&pwqt, g_wqt);
    cudaGetSymbolAddress((void**)&pwkt, g_wkt);
    cudaGetSymbolAddress((void**)&pwvt, g_wvt);
    cudaGetSymbolAddress((void**)&pwot, g_wot);
    cudaGetSymbolAddress((void**)&pw1t, g_w1t);
    cudaGetSymbolAddress((void**)&pw2t, g_w2t);
    cudaGetSymbolAddress((void**)&pembr, g_embr);

    cudaFuncSetAttribute((const void*)gemm_kernel<0, true>,  cudaFuncAttributeMaxDynamicSharedMemorySize, SMEM_TOTAL);
    cudaFuncSetAttribute((const void*)gemm_kernel<0, false>, cudaFuncAttributeMaxDynamicSharedMemorySize, SMEM_TOTAL);
    cudaFuncSetAttribute((const void*)gemm_kernel<1, true>,  cudaFuncAttributeMaxDynamicSharedMemorySize, SMEM_TOTAL);
    cudaFuncSetAttribute((const void*)gemm_kernel<2, true>,  cudaFuncAttributeMaxDynamicSharedMemorySize, SMEM_TOTAL);
    cudaFuncSetAttribute((const void*)gemm_kernel<3, true>,  cudaFuncAttributeMaxDynamicSharedMemorySize, SMEM_TOTAL);
    cudaFuncSetAttribute((const void*)qkv_kernel,            cudaFuncAttributeMaxDynamicSharedMemorySize, SMEM_TOTAL);

    dim3 gT(Dm / 32, Dm / 32, Ll);
    transpose_rna_kernel<<<gT, 256>>>(wq, pwqt, Dm, Dm);
    transpose_rna_kernel<<<gT, 256>>>(wk, pwkt, Dm, Dm);
    transpose_rna_kernel<<<gT, 256>>>(wv, pwvt, Dm, Dm);
    transpose_rna_kernel<<<gT, 256>>>(wo, pwot, Dm, Dm);
    dim3 gT1(FFd / 32, Dm / 32, Ll);
    transpose_rna_kernel<<<gT1, 256>>>(w1, pw1t, Dm, FFd);
    dim3 gT2(Dm / 32, FFd / 32, Ll);
    transpose_rna_kernel<<<gT2, 256>>>(w2, pw2t, FFd, Dm);
    round_emb_kernel<<<Vv, 256>>>(tok_emb, pembr);

    embed_kernel<<<MROWS * Dm / 4 / 256, 256>>>(tokens, tok_emb, pos_emb);

    dim3 gD(Dm / 128, MROWS / 128);        // (8,16)
    dim3 gQKV(Dm / 128, MROWS / 128, 3);   // (8,16,3)
    dim3 gFF(FFd / 128, MROWS / 128);      // (32,16)
    dim3 gAttn(Sq / 64, Hh, Bz);

    for (int l = 0; l < Ll; l++) {
        const float* lWqt = pwqt + (size_t)l * Dm * Dm;
        const float* lWkt = pwkt + (size_t)l * Dm * Dm;
        const float* lWvt = pwvt + (size_t)l * Dm * Dm;
        const float* lWot = pwot + (size_t)l * Dm * Dm;
        const float* lW1t = pw1t + (size_t)l * Dm * FFd;
        const float* lW2t = pw2t + (size_t)l * FFd * Dm;
        const float* lB1 = b1 + (size_t)l * FFd;
        const float* lB2 = b2 + (size_t)l * Dm;

        ln_kernel<<<MROWS, 256>>>(px, ln1_g + (size_t)l * Dm, ln1_b + (size_t)l * Dm, ph);
        qkv_kernel<<<gQKV, 256, SMEM_TOTAL>>>(ph, lWqt, lWkt, lWvt, pq, pk, pv);
        attn_kernel<<<gAttn, 256>>>(pq, pk, pv, pa);
        gemm_kernel<1, true><<<gD, 256, SMEM_TOTAL>>>(pa, lWot, nullptr, px, px, MROWS, Dm, Dm);
        ln_kernel<<<MROWS, 256>>>(px, ln2_g + (size_t)l * Dm, ln2_b + (size_t)l * Dm, ph);
        gemm_kernel<2, true><<<gFF, 256, SMEM_TOTAL>>>(ph, lW1t, lB1, nullptr, pf, MROWS, FFd, Dm);
        gemm_kernel<3, true><<<gD, 256, SMEM_TOTAL>>>(pf, lW2t, lB2, px, px, MROWS, Dm, FFd);
    }

    ln_kernel<<<MROWS, 256>>>(px, lnf_g, lnf_b, ph);
    dim3 gLog((Vv + 127) / 128, MROWS / 128);  // (393,16)
    gemm_kernel<0, false><<<gLog, 256, SMEM_TOTAL>>>(ph, pembr, nullptr, nullptr, out, MROWS, Vv, Dm);
}

// round 8
// speedup vs baseline: 1.0839x; 1.0569x over previous
#include <cuda_runtime.h>
#include <math.h>
#include <stdint.h>

#define Bz 2
#define Sq 1024
#define Dm 1024
#define Hh 16
#define Ll 6
#define Vv 50257
#define HDm 64
#define MROWS (Bz * Sq)
#define FFd (4 * Dm)

__device__ float g_x[MROWS * Dm];
__device__ float g_h[MROWS * Dm];
__device__ float g_q[MROWS * Dm];
__device__ float g_k[MROWS * Dm];
__device__ float g_v[MROWS * Dm];
__device__ float g_att[MROWS * Dm];
__device__ float g_ff[MROWS * FFd];
__device__ float g_wqt[Ll * Dm * Dm];
__device__ float g_wkt[Ll * Dm * Dm];
__device__ float g_wvt[Ll * Dm * Dm];
__device__ float g_wot[Ll * Dm * Dm];
__device__ float g_w1t[(size_t)Ll * Dm * FFd];
__device__ float g_w2t[(size_t)Ll * FFd * Dm];
__device__ float g_embr[(size_t)Vv * Dm];

__device__ __forceinline__ float rnaf(float x) {
    uint32_t u;
    asm("cvt.rna.tf32.f32 %0, %1;" : "=r"(u) : "f"(x));
    return __uint_as_float(u);
}
__device__ __forceinline__ void cpasync16(void* sdst, const void* gsrc) {
    uint32_t d = (uint32_t)__cvta_generic_to_shared(sdst);
    asm volatile("cp.async.cg.shared.global [%0], [%1], 16;" :: "r"(d), "l"(gsrc));
}
__device__ __forceinline__ void mma_tf32(float* c, const uint32_t* a, const uint32_t* b) {
    asm volatile(
        "mma.sync.aligned.m16n8k8.row.col.f32.tf32.tf32.f32 "
        "{%0,%1,%2,%3}, {%4,%5,%6,%7}, {%8,%9}, {%0,%1,%2,%3};"
        : "+f"(c[0]), "+f"(c[1]), "+f"(c[2]), "+f"(c[3])
        : "r"(a[0]), "r"(a[1]), "r"(a[2]), "r"(a[3]), "r"(b[0]), "r"(b[1]));
}

// ---------------------------------------------------------------------------
__global__ void embed_kernel(const int* __restrict__ tokens,
                             const float* __restrict__ tok_emb,
                             const float* __restrict__ pos_emb) {
    int idx = blockIdx.x * blockDim.x + threadIdx.x;
    if (idx >= MROWS * Dm / 4) return;
    int row = idx / (Dm / 4), c4 = idx % (Dm / 4), s = row % Sq;
    int tok = tokens[row];
    float4 te = reinterpret_cast<const float4*>(tok_emb + (size_t)tok * Dm)[c4];
    float4 pe = reinterpret_cast<const float4*>(pos_emb + (size_t)s * Dm)[c4];
    te.x += pe.x; te.y += pe.y; te.z += pe.z; te.w += pe.w;
    reinterpret_cast<float4*>(g_x)[idx] = te;
}

// 4-way fused transpose for the D x D weights: grid.z = 4*Ll
__global__ __launch_bounds__(256) void transpose4_rna_kernel(
    const float* __restrict__ wq, const float* __restrict__ wk,
    const float* __restrict__ wv, const float* __restrict__ wo,
    float* __restrict__ oq, float* __restrict__ ok,
    float* __restrict__ ov, float* __restrict__ oo) {
    __shared__ float t[32][33];
    int which = blockIdx.z / Ll, l = blockIdx.z % Ll;
    const float* W = (which == 0) ? wq : (which == 1) ? wk : (which == 2) ? wv : wo;
    float* O = (which == 0) ? oq : (which == 1) ? ok : (which == 2) ? ov : oo;
    const float* Wl = W + (size_t)l * Dm * Dm;
    float* Ol = O + (size_t)l * Dm * Dm;
    int n0 = blockIdx.x * 32, k0 = blockIdx.y * 32;
    int tx = threadIdx.x & 31, ty = threadIdx.x >> 5;
#pragma unroll
    for (int i = 0; i < 32; i += 8)
        t[ty + i][tx] = Wl[(size_t)(k0 + ty + i) * Dm + n0 + tx];
    __syncthreads();
#pragma unroll
    for (int i = 0; i < 32; i += 8)
        Ol[(size_t)(n0 + ty + i) * Dm + k0 + tx] = rnaf(t[tx][ty + i]);
}

__global__ __launch_bounds__(256) void transpose_rna_kernel(const float* __restrict__ W,
                                                            float* __restrict__ WT, int K, int N) {
    __shared__ float t[32][33];
    const float* Wl = W + (size_t)blockIdx.z * K * N;
    float* WTl = WT + (size_t)blockIdx.z * K * N;
    int n0 = blockIdx.x * 32, k0 = blockIdx.y * 32;
    int tx = threadIdx.x & 31, ty = threadIdx.x >> 5;
#pragma unroll
    for (int i = 0; i < 32; i += 8)
        t[ty + i][tx] = Wl[(size_t)(k0 + ty + i) * N + n0 + tx];
    __syncthreads();
#pragma unroll
    for (int i = 0; i < 32; i += 8)
        WTl[(size_t)(n0 + ty + i) * K + k0 + tx] = rnaf(t[tx][ty + i]);
}

__global__ __launch_bounds__(256) void round_emb_kernel(const float* __restrict__ E, float* __restrict__ O) {
    size_t base = (size_t)blockIdx.x * Dm + threadIdx.x * 4;
    float4 v = *reinterpret_cast<const float4*>(E + base);
    v.x = rnaf(v.x); v.y = rnaf(v.y); v.z = rnaf(v.z); v.w = rnaf(v.w);
    *reinterpret_cast<float4*>(O + base) = v;
}

__global__ __launch_bounds__(256) void ln_kernel(const float* __restrict__ x,
                                                 const float* __restrict__ gw,
                                                 const float* __restrict__ bw,
                                                 float* __restrict__ out) {
    int row = blockIdx.x, tid = threadIdx.x;
    const float* xr = x + (size_t)row * Dm;
    float v[4], s = 0.f, s2 = 0.f;
#pragma unroll
    for (int i = 0; i < 4; i++) { v[i] = xr[tid + i * 256]; s += v[i]; s2 += v[i] * v[i]; }
#pragma unroll
    for (int o = 16; o > 0; o >>= 1) {
        s += __shfl_xor_sync(0xffffffffu, s, o);
        s2 += __shfl_xor_sync(0xffffffffu, s2, o);
    }
    __shared__ float ws[8], ws2[8];
    int w = tid >> 5, l = tid & 31;
    if (l == 0) { ws[w] = s; ws2[w] = s2; }
    __syncthreads();
    s = 0.f; s2 = 0.f;
#pragma unroll
    for (int i = 0; i < 8; i++) { s += ws[i]; s2 += ws2[i]; }
    float mean = s * (1.0f / Dm);
    float var = s2 * (1.0f / Dm) - mean * mean;
    float rstd = rsqrtf(var + 1e-5f);
    float* orow = out + (size_t)row * Dm;
#pragma unroll
    for (int i = 0; i < 4; i++) {
        int col = tid + i * 256;
        orow[col] = rnaf((v[i] - mean) * rstd * gw[col] + bw[col]);
    }
}

// ---------------------------------------------------------------------------
// TF32 mma.sync GEMM: C = A[M,K] @ Bt[N,K]^T, tf32-prerounded inputs.
// CTA 128x128, BK=32, 3-stage cp.async, 256 threads, warp 64x32.
// SW128 XOR-swizzled smem rows (128B, no pad) -> conflict-free STS + LDS,
// stage = 32KB, 3 stages = 96KB -> 2 CTAs/SM (launch_bounds(256,2)).
// SWAP: take m-block from blockIdx.x (logits L2 reuse). VEC: even-N float2 stores.
// ---------------------------------------------------------------------------
#define STAGE_BYTES (2 * 128 * 128)     // 32768
#define SMEM_TOTAL (3 * STAGE_BYTES)    // 98304

template <int OP, bool VEC, bool SWAP>
__device__ __forceinline__ void gemm_body(const float* __restrict__ A, const float* __restrict__ Bt,
                                          const float* __restrict__ bias, const float* __restrict__ res,
                                          float* __restrict__ C, int M, int N, int K) {
    extern __shared__ char smem[];
    const int m0 = (SWAP ? blockIdx.x : blockIdx.y) * 128;
    const int n0 = (SWAP ? blockIdx.y : blockIdx.x) * 128;
    int tid = threadIdx.x, warp = tid >> 5, lane = tid & 31;
    int g = lane >> 2, tg = lane & 3;
    int wm = warp & 1, wn = warp >> 1;

    float acc[4][4][4];
#pragma unroll
    for (int mt = 0; mt < 4; mt++)
#pragma unroll
        for (int nt = 0; nt < 4; nt++)
#pragma unroll
            for (int i = 0; i < 4; i++) acc[mt][nt][i] = 0.f;

    const int KT = K / 32;

    auto loadStage = [&](int stg) {
        char* base = smem + (stg % 3) * STAGE_BYTES;
        char* sa = base;
        char* sbf = base + 128 * 128;
        const float* Ak = A + (size_t)m0 * K + stg * 32;
        const float* Bk = Bt + stg * 32;
#pragma unroll
        for (int p = 0; p < 4; p++) {
            int id = tid + p * 256, r = id >> 3, c = id & 7;
            cpasync16(sa + r * 128 + ((c ^ (r & 7)) * 16), Ak + (size_t)r * K + c * 4);
        }
#pragma unroll
        for (int p = 0; p < 4; p++) {
            int id = tid + p * 256, r = id >> 3, c = id & 7;
            int n = n0 + r; if (n >= N) n = N - 1;
            cpasync16(sbf + r * 128 + ((c ^ (r & 7)) * 16), Bk + (size_t)n * K + c * 4);
        }
        asm volatile("cp.async.commit_group;");
    };

    loadStage(0);
    loadStage(1);

    for (int j = 0; j < KT; j++) {
        if (j + 1 < KT) asm volatile("cp.async.wait_group 1;");
        else            asm volatile("cp.async.wait_group 0;");
        __syncthreads();
        if (j + 2 < KT) loadStage(j + 2);

        const uint32_t* As = reinterpret_cast<const uint32_t*>(smem + (j % 3) * STAGE_BYTES);
        const uint32_t* Bs = As + 128 * 32;

        // swizzled word offset within a 32-word row: (w>>2 ^ (row&7))*4 + (w&3)
#pragma unroll
        for (int kk = 0; kk < 4; kk++) {
            int kb = kk * 8;
            int ch0 = kb >> 2, ch1 = ch0 + 1;   // chunks for w=kb+tg, kb+tg+4
            uint32_t afr[4][4];
#pragma unroll
            for (int mt = 0; mt < 4; mt++) {
                int rA = wm * 64 + mt * 16 + g;      // row in [0,128)
                int rB = rA + 8;
                int sA0 = rA * 32 + ((ch0 ^ (rA & 7)) << 2) + tg;
                int sA1 = rB * 32 + ((ch0 ^ (rB & 7)) << 2) + tg;
                int sA2 = rA * 32 + ((ch1 ^ (rA & 7)) << 2) + tg;
                int sA3 = rB * 32 + ((ch1 ^ (rB & 7)) << 2) + tg;
                afr[mt][0] = As[sA0];
                afr[mt][1] = As[sA1];
                afr[mt][2] = As[sA2];
                afr[mt][3] = As[sA3];
            }
            uint32_t bfr[4][2];
#pragma unroll
            for (int nt = 0; nt < 4; nt++) {
                int rN = wn * 32 + nt * 8 + g;
                bfr[nt][0] = Bs[rN * 32 + ((ch0 ^ (rN & 7)) << 2) + tg];
                bfr[nt][1] = Bs[rN * 32 + ((ch1 ^ (rN & 7)) << 2) + tg];
            }
#pragma unroll
            for (int mt = 0; mt < 4; mt++)
#pragma unroll
                for (int nt = 0; nt < 4; nt++)
                    mma_tf32(acc[mt][nt], afr[mt], bfr[nt]);
        }
    }

#pragma unroll
    for (int mt = 0; mt < 4; mt++) {
#pragma unroll
        for (int half = 0; half < 2; half++) {
            int m = m0 + wm * 64 + mt * 16 + g + half * 8;
#pragma unroll
            for (int nt = 0; nt < 4; nt++) {
                int col = n0 + wn * 32 + nt * 8 + tg * 2;
                float v0 = acc[mt][nt][half * 2 + 0];
                float v1 = acc[mt][nt][half * 2 + 1];
                if (OP == 2 || OP == 3) { v0 += bias[col]; v1 += bias[col + 1]; }
                if (OP == 2) {
                    v0 = rnaf(0.5f * v0 * (1.0f + erff(v0 * 0.70710678118654752f)));
                    v1 = rnaf(0.5f * v1 * (1.0f + erff(v1 * 0.70710678118654752f)));
                }
                if (OP == 1 || OP == 3) {
                    float2 r = *reinterpret_cast<const float2*>(res + (size_t)m * N + col);
                    v0 += r.x; v1 += r.y;
                }
                if (VEC) {
                    float2 o; o.x = v0; o.y = v1;
                    *reinterpret_cast<float2*>(C + (size_t)m * N + col) = o;
                } else {
                    if (col < N)     C[(size_t)m * N + col]     = v0;
                    if (col + 1 < N) C[(size_t)m * N + col + 1] = v1;
                }
            }
        }
    }
}

template <int OP, bool VEC, bool SWAP>
__global__ __launch_bounds__(256, 2) void gemm_kernel(const float* __restrict__ A, const float* __restrict__ Bt,
                                                      const float* __restrict__ bias, const float* __restrict__ res,
                                                      float* __restrict__ C, int M, int N, int K) {
    gemm_body<OP, VEC, SWAP>(A, Bt, bias, res, C, M, N, K);
}

__global__ __launch_bounds__(256, 2) void qkv_kernel(const float* __restrict__ A, const float* __restrict__ Wqt,
                                                     const float* __restrict__ Wkt, const float* __restrict__ Wvt,
                                                     float* __restrict__ Qo, float* __restrict__ Ko,
                                                     float* __restrict__ Vo) {
    const float* Bt = (blockIdx.z == 0) ? Wqt : (blockIdx.z == 1 ? Wkt : Wvt);
    float* C = (blockIdx.z == 0) ? Qo : (blockIdx.z == 1 ? Ko : Vo);
    gemm_body<0, true, false>(A, Bt, nullptr, nullptr, C, MROWS, Dm, Dm);
}

// ---------------------------------------------------------------------------
__global__ __launch_bounds__(256) void attn_kernel(const float* __restrict__ Qg,
                                                   const float* __restrict__ Kg,
                                                   const float* __restrict__ Vg,
                                                   float* __restrict__ Og) {
    __shared__ float Qs[64][64];
    __shared__ float Ks[64][64];
    __shared__ float Vs[64][64];
    int b = blockIdx.z, h = blockIdx.y, qi = blockIdx.x;
    int tid = threadIdx.x;
    for (int t = tid; t < 1024; t += 256) {
        int r = t >> 4, c4 = t & 15;
        float4 v = *reinterpret_cast<const float4*>(
            Qg + ((size_t)(b * Sq + qi * 64 + r) * Dm) + h * HDm + c4 * 4);
        *reinterpret_cast<float4*>(&Qs[r][c4 * 4]) = v;
    }
    int q = tid >> 2, c = tid & 3;
    float m_i = -INFINITY, l_i = 0.f;
    float o[16];
#pragma unroll
    for (int d = 0; d < 16; d++) o[d] = 0.f;
    const float scale = 0.125f;
    int qg = qi * 64 + q;

    for (int j = 0; j <= qi; j++) {
        __syncthreads();
        for (int t = tid; t < 1024; t += 256) {
            int r = t >> 4, c4 = t & 15;
            size_t base = ((size_t)(b * Sq + j * 64 + r) * Dm) + h * HDm + c4 * 4;
            *reinterpret_cast<float4*>(&Ks[r][c4 * 4]) = *reinterpret_cast<const float4*>(Kg + base);
            *reinterpret_cast<float4*>(&Vs[r][c4 * 4]) = *reinterpret_cast<const float4*>(Vg + base);
        }
        __syncthreads();
        float s[16];
#pragma unroll
        for (int kk = 0; kk < 16; kk++) s[kk] = 0.f;
#pragma unroll 4
        for (int kd4 = 0; kd4 < 16; kd4++) {
            float4 qv = *reinterpret_cast<const float4*>(&Qs[q][kd4 * 4]);
#pragma unroll
            for (int kk = 0; kk < 16; kk++) {
                float4 kv = *reinterpret_cast<const float4*>(&Ks[c * 16 + kk][kd4 * 4]);
                s[kk] += qv.x * kv.x + qv.y * kv.y + qv.z * kv.z + qv.w * kv.w;
            }
        }
#pragma unroll
        for (int kk = 0; kk < 16; kk++) {
            int kg = j * 64 + c * 16 + kk;
            s[kk] = (kg <= qg) ? s[kk] * scale : -INFINITY;
        }
        float mloc = s[0];
#pragma unroll
        for (int kk = 1; kk < 16; kk++) mloc = fmaxf(mloc, s[kk]);
        mloc = fmaxf(mloc, __shfl_xor_sync(0xffffffffu, mloc, 1, 4));
        mloc = fmaxf(mloc, __shfl_xor_sync(0xffffffffu, mloc, 2, 4));
        float mnew = fmaxf(m_i, mloc);
        float alpha = expf(m_i - mnew);
        float p[16], lloc = 0.f;
#pragma unroll
        for (int kk = 0; kk < 16; kk++) { p[kk] = expf(s[kk] - mnew); lloc += p[kk]; }
        lloc += __shfl_xor_sync(0xffffffffu, lloc, 1, 4);
        lloc += __shfl_xor_sync(0xffffffffu, lloc, 2, 4);
        l_i = l_i * alpha + lloc;
        m_i = mnew;
#pragma unroll
        for (int d = 0; d < 16; d++) o[d] *= alpha;
#pragma unroll
        for (int src = 0; src < 4; src++) {
#pragma unroll
            for (int kk = 0; kk < 16; kk++) {
                float pv = __shfl_sync(0xffffffffu, p[kk], src, 4);
                int key = src * 16 + kk;
#pragma unroll
                for (int d4 = 0; d4 < 4; d4++) {
                    float4 vv = *reinterpret_cast<const float4*>(&Vs[key][c * 16 + d4 * 4]);
                    o[d4 * 4 + 0] += pv * vv.x;
                    o[d4 * 4 + 1] += pv * vv.y;
                    o[d4 * 4 + 2] += pv * vv.z;
                    o[d4 * 4 + 3] += pv * vv.w;
                }
            }
        }
    }
    float inv = 1.0f / l_i;
    size_t obase = ((size_t)(b * Sq + qi * 64 + q) * Dm) + h * HDm + c * 16;
#pragma unroll
    for (int d4 = 0; d4 < 4; d4++) {
        float4 ov;
        ov.x = rnaf(o[d4 * 4 + 0] * inv);
        ov.y = rnaf(o[d4 * 4 + 1] * inv);
        ov.z = rnaf(o[d4 * 4 + 2] * inv);
        ov.w = rnaf(o[d4 * 4 + 3] * inv);
        *reinterpret_cast<float4*>(Og + obase + d4 * 4) = ov;
    }
}

// ---------------------------------------------------------------------------
extern "C" void kernel_launch(void* const* d_in, const int* in_sizes, int n_in,
                              void* d_out, int out_size) {
    const int*   tokens  = (const int*)d_in[0];
    const float* tok_emb = (const float*)d_in[1];
    const float* pos_emb = (const float*)d_in[2];
    const float* ln1_g = (const float*)d_in[3];
    const float* ln1_b = (const float*)d_in[4];
    const float* wq = (const float*)d_in[5];
    const float* wk = (const float*)d_in[6];
    const float* wv = (const float*)d_in[7];
    const float* wo = (const float*)d_in[8];
    const float* ln2_g = (const float*)d_in[9];
    const float* ln2_b = (const float*)d_in[10];
    const float* w1 = (const float*)d_in[11];
    const float* b1 = (const float*)d_in[12];
    const float* w2 = (const float*)d_in[13];
    const float* b2 = (const float*)d_in[14];
    const float* lnf_g = (const float*)d_in[15];
    const float* lnf_b = (const float*)d_in[16];
    float* out = (float*)d_out;

    float *px, *ph, *pq, *pk, *pv, *pa, *pf, *pwqt, *pwkt, *pwvt, *pwot, *pw1t, *pw2t, *pembr;
    cudaGetSymbolAddress((void**)&px, g_x);
    cudaGetSymbolAddress((void**)&ph, g_h);
    cudaGetSymbolAddress((void**)&pq, g_q);
    cudaGetSymbolAddress((void**)&pk, g_k);
    cudaGetSymbolAddress((void**)&pv, g_v);
    cudaGetSymbolAddress((void**)&pa, g_att);
    cudaGetSymbolAddress((void**)&pf, g_ff);
    cudaGetSymbolAddress((void**)&pwqt, g_wqt);
    cudaGetSymbolAddress((void**)&pwkt, g_wkt);
    cudaGetSymbolAddress((void**)&pwvt, g_wvt);
    cudaGetSymbolAddress((void**)&pwot, g_wot);
    cudaGetSymbolAddress((void**)&pw1t, g_w1t);
    cudaGetSymbolAddress((void**)&pw2t, g_w2t);
    cudaGetSymbolAddress((void**)&pembr, g_embr);

    cudaFuncSetAttribute((const void*)gemm_kernel<0, false, true>, cudaFuncAttributeMaxDynamicSharedMemorySize, SMEM_TOTAL);
    cudaFuncSetAttribute((const void*)gemm_kernel<1, true, false>, cudaFuncAttributeMaxDynamicSharedMemorySize, SMEM_TOTAL);
    cudaFuncSetAttribute((const void*)gemm_kernel<2, true, false>, cudaFuncAttributeMaxDynamicSharedMemorySize, SMEM_TOTAL);
    cudaFuncSetAttribute((const void*)gemm_kernel<3, true, false>, cudaFuncAttributeMaxDynamicSharedMemorySize, SMEM_TOTAL);
    cudaFuncSetAttribute((const void*)qkv_kernel,                  cudaFuncAttributeMaxDynamicSharedMemorySize, SMEM_TOTAL);

    // launch order: 0 t4, 1 t_w1, 2 t_w2, 3 embed, 4 ln1, 5 qkv  (ncu -s 5 hits qkv)
    dim3 gT4(Dm / 32, Dm / 32, 4 * Ll);
    transpose4_rna_kernel<<<gT4, 256>>>(wq, wk, wv, wo, pwqt, pwkt, pwvt, pwot);
    dim3 gT1(FFd / 32, Dm / 32, Ll);
    transpose_rna_kernel<<<gT1, 256>>>(w1, pw1t, Dm, FFd);
    dim3 gT2(Dm / 32, FFd / 32, Ll);
    transpose_rna_kernel<<<gT2, 256>>>(w2, pw2t, FFd, Dm);

    embed_kernel<<<MROWS * Dm / 4 / 256, 256>>>(tokens, tok_emb, pos_emb);

    dim3 gD(Dm / 128, MROWS / 128);        // (8,16)
    dim3 gQKV(Dm / 128, MROWS / 128, 3);
    dim3 gFF(FFd / 128, MROWS / 128);      // (32,16)
    dim3 gAttn(Sq / 64, Hh, Bz);

    for (int l = 0; l < Ll; l++) {
        const float* lWqt = pwqt + (size_t)l * Dm * Dm;
        const float* lWkt = pwkt + (size_t)l * Dm * Dm;
        const float* lWvt = pwvt + (size_t)l * Dm * Dm;
        const float* lWot = pwot + (size_t)l * Dm * Dm;
        const float* lW1t = pw1t + (size_t)l * Dm * FFd;
        const float* lW2t = pw2t + (size_t)l * FFd * Dm;
        const float* lB1 = b1 + (size_t)l * FFd;
        const float* lB2 = b2 + (size_t)l * Dm;

        ln_kernel<<<MROWS, 256>>>(px, ln1_g + (size_t)l * Dm, ln1_b + (size_t)l * Dm, ph);
        qkv_kernel<<<gQKV, 256, SMEM_TOTAL>>>(ph, lWqt, lWkt, lWvt, pq, pk, pv);
        attn_kernel<<<gAttn, 256>>>(pq, pk, pv, pa);
        gemm_kernel<1, true, false><<<gD, 256, SMEM_TOTAL>>>(pa, lWot, nullptr, px, px, MROWS, Dm, Dm);
        ln_kernel<<<MROWS, 256>>>(px, ln2_g + (size_t)l * Dm, ln2_b + (size_t)l * Dm, ph);
        gemm_kernel<2, true, false><<<gFF, 256, SMEM_TOTAL>>>(ph, lW1t, lB1, nullptr, pf, MROWS, FFd, Dm);
        gemm_kernel<3, true, false><<<gD, 256, SMEM_TOTAL>>>(pf, lW2t, lB2, px, px, MROWS, Dm, FFd);
    }

    ln_kernel<<<MROWS, 256>>>(px, lnf_g, lnf_b, ph);
    round_emb_kernel<<<Vv, 256>>>(tok_emb, pembr);
    dim3 gLog(MROWS / 128, (Vv + 127) / 128);  // SWAP: x=m-blocks(16), y=n-blocks(393)
    gemm_kernel<0, false, true><<<gLog, 256, SMEM_TOTAL>>>(ph, pembr, nullptr, nullptr, out, MROWS, Vv, Dm);
}

// round 9
// speedup vs baseline: 1.2265x; 1.1316x over previous
#include <cuda_runtime.h>
#include <cuda_fp16.h>
#include <math.h>
#include <stdint.h>

#define Bz 2
#define Sq 1024
#define Dm 1024
#define Hh 16
#define Ll 6
#define Vv 50257
#define HDm 64
#define MROWS (Bz * Sq)
#define FFd (4 * Dm)

__device__ float  g_x[MROWS * Dm];              // fp32 residual stream
__device__ __half g_h[MROWS * Dm];
__device__ __half g_q[MROWS * Dm];
__device__ __half g_k[MROWS * Dm];
__device__ __half g_v[MROWS * Dm];
__device__ __half g_att[MROWS * Dm];
__device__ __half g_ff[MROWS * FFd];
__device__ __half g_wqt[Ll * Dm * Dm];
__device__ __half g_wkt[Ll * Dm * Dm];
__device__ __half g_wvt[Ll * Dm * Dm];
__device__ __half g_wot[Ll * Dm * Dm];
__device__ __half g_w1t[(size_t)Ll * Dm * FFd];
__device__ __half g_w2t[(size_t)Ll * FFd * Dm];
__device__ __half g_embh[(size_t)Vv * Dm];

__device__ __forceinline__ void cpasync16(void* sdst, const void* gsrc) {
    uint32_t d = (uint32_t)__cvta_generic_to_shared(sdst);
    asm volatile("cp.async.cg.shared.global [%0], [%1], 16;" :: "r"(d), "l"(gsrc));
}
__device__ __forceinline__ void mma_f16(float* c, const uint32_t* a, const uint32_t* b) {
    asm volatile(
        "mma.sync.aligned.m16n8k16.row.col.f32.f16.f16.f32 "
        "{%0,%1,%2,%3}, {%4,%5,%6,%7}, {%8,%9}, {%0,%1,%2,%3};"
        : "+f"(c[0]), "+f"(c[1]), "+f"(c[2]), "+f"(c[3])
        : "r"(a[0]), "r"(a[1]), "r"(a[2]), "r"(a[3]), "r"(b[0]), "r"(b[1]));
}
__device__ __forceinline__ void store2(__half* C, size_t idx, float v0, float v1) {
    *reinterpret_cast<__half2*>(C + idx) = __floats2half2_rn(v0, v1);
}
__device__ __forceinline__ void store2(float* C, size_t idx, float v0, float v1) {
    float2 o; o.x = v0; o.y = v1;
    *reinterpret_cast<float2*>(C + idx) = o;
}

// ---------------------------------------------------------------------------
__global__ void embed_kernel(const int* __restrict__ tokens,
                             const float* __restrict__ tok_emb,
                             const float* __restrict__ pos_emb) {
    int idx = blockIdx.x * blockDim.x + threadIdx.x;
    if (idx >= MROWS * Dm / 4) return;
    int row = idx / (Dm / 4), c4 = idx % (Dm / 4), s = row % Sq;
    int tok = tokens[row];
    float4 te = reinterpret_cast<const float4*>(tok_emb + (size_t)tok * Dm)[c4];
    float4 pe = reinterpret_cast<const float4*>(pos_emb + (size_t)s * Dm)[c4];
    te.x += pe.x; te.y += pe.y; te.z += pe.z; te.w += pe.w;
    reinterpret_cast<float4*>(g_x)[idx] = te;
}

// 4-way fused transpose (D x D weights) -> half, grid.z = 4*Ll
__global__ __launch_bounds__(256) void transpose4_h_kernel(
    const float* __restrict__ wq, const float* __restrict__ wk,
    const float* __restrict__ wv, const float* __restrict__ wo,
    __half* __restrict__ oq, __half* __restrict__ ok,
    __half* __restrict__ ov, __half* __restrict__ oo) {
    __shared__ float t[32][33];
    int which = blockIdx.z / Ll, l = blockIdx.z % Ll;
    const float* W = (which == 0) ? wq : (which == 1) ? wk : (which == 2) ? wv : wo;
    __half* O = (which == 0) ? oq : (which == 1) ? ok : (which == 2) ? ov : oo;
    const float* Wl = W + (size_t)l * Dm * Dm;
    __half* Ol = O + (size_t)l * Dm * Dm;
    int n0 = blockIdx.x * 32, k0 = blockIdx.y * 32;
    int tx = threadIdx.x & 31, ty = threadIdx.x >> 5;
#pragma unroll
    for (int i = 0; i < 32; i += 8)
        t[ty + i][tx] = Wl[(size_t)(k0 + ty + i) * Dm + n0 + tx];
    __syncthreads();
#pragma unroll
    for (int i = 0; i < 32; i += 8)
        Ol[(size_t)(n0 + ty + i) * Dm + k0 + tx] = __float2half(t[tx][ty + i]);
}

__global__ __launch_bounds__(256) void transpose_h_kernel(const float* __restrict__ W,
                                                          __half* __restrict__ WT, int K, int N) {
    __shared__ float t[32][33];
    const float* Wl = W + (size_t)blockIdx.z * K * N;
    __half* WTl = WT + (size_t)blockIdx.z * K * N;
    int n0 = blockIdx.x * 32, k0 = blockIdx.y * 32;
    int tx = threadIdx.x & 31, ty = threadIdx.x >> 5;
#pragma unroll
    for (int i = 0; i < 32; i += 8)
        t[ty + i][tx] = Wl[(size_t)(k0 + ty + i) * N + n0 + tx];
    __syncthreads();
#pragma unroll
    for (int i = 0; i < 32; i += 8)
        WTl[(size_t)(n0 + ty + i) * K + k0 + tx] = __float2half(t[tx][ty + i]);
}

__global__ __launch_bounds__(256) void emb_h_kernel(const float* __restrict__ E, __half* __restrict__ O) {
    size_t base = (size_t)blockIdx.x * Dm + threadIdx.x * 4;
    float4 v = *reinterpret_cast<const float4*>(E + base);
    __half2 h0 = __floats2half2_rn(v.x, v.y);
    __half2 h1 = __floats2half2_rn(v.z, v.w);
    uint2 u;
    u.x = *reinterpret_cast<uint32_t*>(&h0);
    u.y = *reinterpret_cast<uint32_t*>(&h1);
    *reinterpret_cast<uint2*>(O + base) = u;
}

__global__ __launch_bounds__(256) void ln_kernel(const float* __restrict__ x,
                                                 const float* __restrict__ gw,
                                                 const float* __restrict__ bw,
                                                 __half* __restrict__ out) {
    int row = blockIdx.x, tid = threadIdx.x;
    const float* xr = x + (size_t)row * Dm;
    float v[4], s = 0.f, s2 = 0.f;
#pragma unroll
    for (int i = 0; i < 4; i++) { v[i] = xr[tid + i * 256]; s += v[i]; s2 += v[i] * v[i]; }
#pragma unroll
    for (int o = 16; o > 0; o >>= 1) {
        s += __shfl_xor_sync(0xffffffffu, s, o);
        s2 += __shfl_xor_sync(0xffffffffu, s2, o);
    }
    __shared__ float ws[8], ws2[8];
    int w = tid >> 5, l = tid & 31;
    if (l == 0) { ws[w] = s; ws2[w] = s2; }
    __syncthreads();
    s = 0.f; s2 = 0.f;
#pragma unroll
    for (int i = 0; i < 8; i++) { s += ws[i]; s2 += ws2[i]; }
    float mean = s * (1.0f / Dm);
    float var = s2 * (1.0f / Dm) - mean * mean;
    float rstd = rsqrtf(var + 1e-5f);
    __half* orow = out + (size_t)row * Dm;
#pragma unroll
    for (int i = 0; i < 4; i++) {
        int col = tid + i * 256;
        orow[col] = __float2half((v[i] - mean) * rstd * gw[col] + bw[col]);
    }
}

// ---------------------------------------------------------------------------
// FP16 mma.sync m16n8k16 GEMM: C = A[M,K] @ Bt[N,K]^T  (A, Bt half; acc fp32)
// CTA 128x128, BK=64 halves (128B rows, SW128 XOR swizzle), 3-stage cp.async,
// 256 threads, warp 64x32.  2 CTAs/SM (96KB smem).
// OP: 0 none, 1 +res, 2 gelu(acc+bias), 3 acc+bias+res.  OutT: __half or float.
// ---------------------------------------------------------------------------
#define STAGE_BYTES (2 * 128 * 128)     // 32768 (A 16KB + B 16KB)
#define SMEM_TOTAL (3 * STAGE_BYTES)    // 98304

template <int OP, bool VEC, bool SWAP, typename OutT>
__device__ __forceinline__ void gemm_body(const __half* __restrict__ A, const __half* __restrict__ Bt,
                                          const float* __restrict__ bias, const float* __restrict__ res,
                                          OutT* __restrict__ C, int M, int N, int K) {
    extern __shared__ char smem[];
    const int m0 = (SWAP ? blockIdx.x : blockIdx.y) * 128;
    const int n0 = (SWAP ? blockIdx.y : blockIdx.x) * 128;
    int tid = threadIdx.x, warp = tid >> 5, lane = tid & 31;
    int g = lane >> 2, tg = lane & 3;
    int wm = warp & 1, wn = warp >> 1;

    float acc[4][4][4];
#pragma unroll
    for (int mt = 0; mt < 4; mt++)
#pragma unroll
        for (int nt = 0; nt < 4; nt++)
#pragma unroll
            for (int i = 0; i < 4; i++) acc[mt][nt][i] = 0.f;

    const int KT = K / 64;

    auto loadStage = [&](int stg) {
        char* base = smem + (stg % 3) * STAGE_BYTES;
        char* sa = base;
        char* sbf = base + 128 * 128;
        const __half* Ak = A + (size_t)m0 * K + stg * 64;
        const __half* Bk = Bt + stg * 64;
#pragma unroll
        for (int p = 0; p < 4; p++) {
            int id = tid + p * 256, r = id >> 3, c = id & 7;
            cpasync16(sa + r * 128 + ((c ^ (r & 7)) * 16), Ak + (size_t)r * K + c * 8);
        }
#pragma unroll
        for (int p = 0; p < 4; p++) {
            int id = tid + p * 256, r = id >> 3, c = id & 7;
            int n = n0 + r; if (n >= N) n = N - 1;
            cpasync16(sbf + r * 128 + ((c ^ (r & 7)) * 16), Bk + (size_t)n * K + c * 8);
        }
        asm volatile("cp.async.commit_group;");
    };

    loadStage(0);
    loadStage(1);

    for (int j = 0; j < KT; j++) {
        if (j + 1 < KT) asm volatile("cp.async.wait_group 1;");
        else            asm volatile("cp.async.wait_group 0;");
        __syncthreads();
        if (j + 2 < KT) loadStage(j + 2);

        // rows are 32 half2-words; word w at swizzled idx: ((w>>2 ^ (r&7))<<2)+(w&3)
        const uint32_t* As = reinterpret_cast<const uint32_t*>(smem + (j % 3) * STAGE_BYTES);
        const uint32_t* Bs = As + 128 * 32;

#pragma unroll
        for (int kk = 0; kk < 8; kk++) {       // 8 x k16 steps = K 128? no: BK=64 -> 4? (64/16=4)
            if (kk >= 4) break;                 // BK=64 halves -> 4 k16 steps
            int ch0 = kk * 2, ch1 = kk * 2 + 1; // words kk*8+tg, kk*8+tg+4
            uint32_t afr[4][4];
#pragma unroll
            for (int mt = 0; mt < 4; mt++) {
                int rA = wm * 64 + mt * 16 + g;
                int rB = rA + 8;
                afr[mt][0] = As[rA * 32 + ((ch0 ^ (rA & 7)) << 2) + tg];
                afr[mt][1] = As[rB * 32 + ((ch0 ^ (rB & 7)) << 2) + tg];
                afr[mt][2] = As[rA * 32 + ((ch1 ^ (rA & 7)) << 2) + tg];
                afr[mt][3] = As[rB * 32 + ((ch1 ^ (rB & 7)) << 2) + tg];
            }
            uint32_t bfr[4][2];
#pragma unroll
            for (int nt = 0; nt < 4; nt++) {
                int rN = wn * 32 + nt * 8 + g;
                bfr[nt][0] = Bs[rN * 32 + ((ch0 ^ (rN & 7)) << 2) + tg];
                bfr[nt][1] = Bs[rN * 32 + ((ch1 ^ (rN & 7)) << 2) + tg];
            }
#pragma unroll
            for (int mt = 0; mt < 4; mt++)
#pragma unroll
                for (int nt = 0; nt < 4; nt++)
                    mma_f16(acc[mt][nt], afr[mt], bfr[nt]);
        }
    }

#pragma unroll
    for (int mt = 0; mt < 4; mt++) {
#pragma unroll
        for (int half = 0; half < 2; half++) {
            int m = m0 + wm * 64 + mt * 16 + g + half * 8;
#pragma unroll
            for (int nt = 0; nt < 4; nt++) {
                int col = n0 + wn * 32 + nt * 8 + tg * 2;
                float v0 = acc[mt][nt][half * 2 + 0];
                float v1 = acc[mt][nt][half * 2 + 1];
                if (OP == 2 || OP == 3) { v0 += bias[col]; v1 += bias[col + 1]; }
                if (OP == 2) {
                    v0 = 0.5f * v0 * (1.0f + erff(v0 * 0.70710678118654752f));
                    v1 = 0.5f * v1 * (1.0f + erff(v1 * 0.70710678118654752f));
                }
                if (OP == 1 || OP == 3) {
                    float2 r = *reinterpret_cast<const float2*>(res + (size_t)m * N + col);
                    v0 += r.x; v1 += r.y;
                }
                if (VEC) {
                    store2(C, (size_t)m * N + col, v0, v1);
                } else {
                    if (col < N)     C[(size_t)m * N + col]     = (OutT)v0;
                    if (col + 1 < N) C[(size_t)m * N + col + 1] = (OutT)v1;
                }
            }
        }
    }
}

template <int OP, bool VEC, bool SWAP, typename OutT>
__global__ __launch_bounds__(256, 2) void gemm_kernel(const __half* __restrict__ A, const __half* __restrict__ Bt,
                                                      const float* __restrict__ bias, const float* __restrict__ res,
                                                      OutT* __restrict__ C, int M, int N, int K) {
    gemm_body<OP, VEC, SWAP, OutT>(A, Bt, bias, res, C, M, N, K);
}

__global__ __launch_bounds__(256, 2) void qkv_kernel(const __half* __restrict__ A, const __half* __restrict__ Wqt,
                                                     const __half* __restrict__ Wkt, const __half* __restrict__ Wvt,
                                                     __half* __restrict__ Qo, __half* __restrict__ Ko,
                                                     __half* __restrict__ Vo) {
    const __half* Bt = (blockIdx.z == 0) ? Wqt : (blockIdx.z == 1 ? Wkt : Wvt);
    __half* C = (blockIdx.z == 0) ? Qo : (blockIdx.z == 1 ? Ko : Vo);
    gemm_body<0, true, false, __half>(A, Bt, nullptr, nullptr, C, MROWS, Dm, Dm);
}

// ---------------------------------------------------------------------------
__global__ __launch_bounds__(256) void attn_kernel(const __half* __restrict__ Qg,
                                                   const __half* __restrict__ Kg,
                                                   const __half* __restrict__ Vg,
                                                   __half* __restrict__ Og) {
    __shared__ float Qs[64][64];
    __shared__ float Ks[64][64];
    __shared__ float Vs[64][64];
    int b = blockIdx.z, h = blockIdx.y, qi = blockIdx.x;
    int tid = threadIdx.x;
    for (int t = tid; t < 512; t += 256) {
        int r = t >> 3, c8 = t & 7;
        const __half2* src = reinterpret_cast<const __half2*>(
            Qg + ((size_t)(b * Sq + qi * 64 + r) * Dm) + h * HDm + c8 * 8);
#pragma unroll
        for (int i = 0; i < 4; i++) {
            float2 f = __half22float2(src[i]);
            Qs[r][c8 * 8 + 2 * i] = f.x;
            Qs[r][c8 * 8 + 2 * i + 1] = f.y;
        }
    }
    int q = tid >> 2, c = tid & 3;
    float m_i = -INFINITY, l_i = 0.f;
    float o[16];
#pragma unroll
    for (int d = 0; d < 16; d++) o[d] = 0.f;
    const float scale = 0.125f;
    int qg = qi * 64 + q;

    for (int j = 0; j <= qi; j++) {
        __syncthreads();
        for (int t = tid; t < 512; t += 256) {
            int r = t >> 3, c8 = t & 7;
            size_t base = ((size_t)(b * Sq + j * 64 + r) * Dm) + h * HDm + c8 * 8;
            const __half2* ks = reinterpret_cast<const __half2*>(Kg + base);
            const __half2* vs = reinterpret_cast<const __half2*>(Vg + base);
#pragma unroll
            for (int i = 0; i < 4; i++) {
                float2 fk = __half22float2(ks[i]);
                float2 fv = __half22float2(vs[i]);
                Ks[r][c8 * 8 + 2 * i] = fk.x; Ks[r][c8 * 8 + 2 * i + 1] = fk.y;
                Vs[r][c8 * 8 + 2 * i] = fv.x; Vs[r][c8 * 8 + 2 * i + 1] = fv.y;
            }
        }
        __syncthreads();
        float s[16];
#pragma unroll
        for (int kk = 0; kk < 16; kk++) s[kk] = 0.f;
#pragma unroll 4
        for (int kd4 = 0; kd4 < 16; kd4++) {
            float4 qv = *reinterpret_cast<const float4*>(&Qs[q][kd4 * 4]);
#pragma unroll
            for (int kk = 0; kk < 16; kk++) {
                float4 kv = *reinterpret_cast<const float4*>(&Ks[c * 16 + kk][kd4 * 4]);
                s[kk] += qv.x * kv.x + qv.y * kv.y + qv.z * kv.z + qv.w * kv.w;
            }
        }
#pragma unroll
        for (int kk = 0; kk < 16; kk++) {
            int kg = j * 64 + c * 16 + kk;
            s[kk] = (kg <= qg) ? s[kk] * scale : -INFINITY;
        }
        float mloc = s[0];
#pragma unroll
        for (int kk = 1; kk < 16; kk++) mloc = fmaxf(mloc, s[kk]);
        mloc = fmaxf(mloc, __shfl_xor_sync(0xffffffffu, mloc, 1, 4));
        mloc = fmaxf(mloc, __shfl_xor_sync(0xffffffffu, mloc, 2, 4));
        float mnew = fmaxf(m_i, mloc);
        float alpha = expf(m_i - mnew);
        float p[16], lloc = 0.f;
#pragma unroll
        for (int kk = 0; kk < 16; kk++) { p[kk] = expf(s[kk] - mnew); lloc += p[kk]; }
        lloc += __shfl_xor_sync(0xffffffffu, lloc, 1, 4);
        lloc += __shfl_xor_sync(0xffffffffu, lloc, 2, 4);
        l_i = l_i * alpha + lloc;
        m_i = mnew;
#pragma unroll
        for (int d = 0; d < 16; d++) o[d] *= alpha;
#pragma unroll
        for (int src = 0; src < 4; src++) {
#pragma unroll
            for (int kk = 0; kk < 16; kk++) {
                float pv = __shfl_sync(0xffffffffu, p[kk], src, 4);
                int key = src * 16 + kk;
#pragma unroll
                for (int d4 = 0; d4 < 4; d4++) {
                    float4 vv = *reinterpret_cast<const float4*>(&Vs[key][c * 16 + d4 * 4]);
                    o[d4 * 4 + 0] += pv * vv.x;
                    o[d4 * 4 + 1] += pv * vv.y;
                    o[d4 * 4 + 2] += pv * vv.z;
                    o[d4 * 4 + 3] += pv * vv.w;
                }
            }
        }
    }
    float inv = 1.0f / l_i;
    __half* op = Og + ((size_t)(b * Sq + qi * 64 + q) * Dm) + h * HDm + c * 16;
#pragma unroll
    for (int d2 = 0; d2 < 8; d2++) {
        *reinterpret_cast<__half2*>(op + d2 * 2) =
            __floats2half2_rn(o[d2 * 2] * inv, o[d2 * 2 + 1] * inv);
    }
}

// ---------------------------------------------------------------------------
extern "C" void kernel_launch(void* const* d_in, const int* in_sizes, int n_in,
                              void* d_out, int out_size) {
    const int*   tokens  = (const int*)d_in[0];
    const float* tok_emb = (const float*)d_in[1];
    const float* pos_emb = (const float*)d_in[2];
    const float* ln1_g = (const float*)d_in[3];
    const float* ln1_b = (const float*)d_in[4];
    const float* wq = (const float*)d_in[5];
    const float* wk = (const float*)d_in[6];
    const float* wv = (const float*)d_in[7];
    const float* wo = (const float*)d_in[8];
    const float* ln2_g = (const float*)d_in[9];
    const float* ln2_b = (const float*)d_in[10];
    const float* w1 = (const float*)d_in[11];
    const float* b1 = (const float*)d_in[12];
    const float* w2 = (const float*)d_in[13];
    const float* b2 = (const float*)d_in[14];
    const float* lnf_g = (const float*)d_in[15];
    const float* lnf_b = (const float*)d_in[16];
    float* out = (float*)d_out;

    float *px;
    __half *ph, *pq, *pk, *pv, *pa, *pf, *pwqt, *pwkt, *pwvt, *pwot, *pw1t, *pw2t, *pembh;
    cudaGetSymbolAddress((void**)&px, g_x);
    cudaGetSymbolAddress((void**)&ph, g_h);
    cudaGetSymbolAddress((void**)&pq, g_q);
    cudaGetSymbolAddress((void**)&pk, g_k);
    cudaGetSymbolAddress((void**)&pv, g_v);
    cudaGetSymbolAddress((void**)&pa, g_att);
    cudaGetSymbolAddress((void**)&pf, g_ff);
    cudaGetSymbolAddress((void**)&pwqt, g_wqt);
    cudaGetSymbolAddress((void**)&pwkt, g_wkt);
    cudaGetSymbolAddress((void**)&pwvt, g_wvt);
    cudaGetSymbolAddress((void**)&pwot, g_wot);
    cudaGetSymbolAddress((void**)&pw1t, g_w1t);
    cudaGetSymbolAddress((void**)&pw2t, g_w2t);
    cudaGetSymbolAddress((void**)&pembh, g_embh);

    cudaFuncSetAttribute((const void*)gemm_kernel<0, false, true, float>,  cudaFuncAttributeMaxDynamicSharedMemorySize, SMEM_TOTAL);
    cudaFuncSetAttribute((const void*)gemm_kernel<1, true, false, float>,  cudaFuncAttributeMaxDynamicSharedMemorySize, SMEM_TOTAL);
    cudaFuncSetAttribute((const void*)gemm_kernel<2, true, false, __half>, cudaFuncAttributeMaxDynamicSharedMemorySize, SMEM_TOTAL);
    cudaFuncSetAttribute((const void*)gemm_kernel<3, true, false, float>,  cudaFuncAttributeMaxDynamicSharedMemorySize, SMEM_TOTAL);
    cudaFuncSetAttribute((const void*)qkv_kernel,                          cudaFuncAttributeMaxDynamicSharedMemorySize, SMEM_TOTAL);

    dim3 gT4(Dm / 32, Dm / 32, 4 * Ll);
    transpose4_h_kernel<<<gT4, 256>>>(wq, wk, wv, wo, pwqt, pwkt, pwvt, pwot);
    dim3 gT1(FFd / 32, Dm / 32, Ll);
    transpose_h_kernel<<<gT1, 256>>>(w1, pw1t, Dm, FFd);
    dim3 gT2(Dm / 32, FFd / 32, Ll);
    transpose_h_kernel<<<gT2, 256>>>(w2, pw2t, FFd, Dm);

    embed_kernel<<<MROWS * Dm / 4 / 256, 256>>>(tokens, tok_emb, pos_emb);

    dim3 gD(Dm / 128, MROWS / 128);
    dim3 gQKV(Dm / 128, MROWS / 128, 3);
    dim3 gFF(FFd / 128, MROWS / 128);
    dim3 gAttn(Sq / 64, Hh, Bz);

    for (int l = 0; l < Ll; l++) {
        const __half* lWqt = pwqt + (size_t)l * Dm * Dm;
        const __half* lWkt = pwkt + (size_t)l * Dm * Dm;
        const __half* lWvt = pwvt + (size_t)l * Dm * Dm;
        const __half* lWot = pwot + (size_t)l * Dm * Dm;
        const __half* lW1t = pw1t + (size_t)l * Dm * FFd;
        const __half* lW2t = pw2t + (size_t)l * FFd * Dm;
        const float* lB1 = b1 + (size_t)l * FFd;
        const float* lB2 = b2 + (size_t)l * Dm;

        ln_kernel<<<MROWS, 256>>>(px, ln1_g + (size_t)l * Dm, ln1_b + (size_t)l * Dm, ph);
        qkv_kernel<<<gQKV, 256, SMEM_TOTAL>>>(ph, lWqt, lWkt, lWvt, pq, pk, pv);
        attn_kernel<<<gAttn, 256>>>(pq, pk, pv, pa);
        gemm_kernel<1, true, false, float><<<gD, 256, SMEM_TOTAL>>>(pa, lWot, nullptr, px, px, MROWS, Dm, Dm);
        ln_kernel<<<MROWS, 256>>>(px, ln2_g + (size_t)l * Dm, ln2_b + (size_t)l * Dm, ph);
        gemm_kernel<2, true, false, __half><<<gFF, 256, SMEM_TOTAL>>>(ph, lW1t, lB1, nullptr, pf, MROWS, FFd, Dm);
        gemm_kernel<3, true, false, float><<<gD, 256, SMEM_TOTAL>>>(pf, lW2t, lB2, px, px, MROWS, Dm, FFd);
    }

    ln_kernel<<<MROWS, 256>>>(px, lnf_g, lnf_b, ph);
    emb_h_kernel<<<Vv, 256>>>(tok_emb, pembh);
    dim3 gLog(MROWS / 128, (Vv + 127) / 128);
    gemm_kernel<0, false, true, float><<<gLog, 256, SMEM_TOTAL>>>(ph, pembh, nullptr, nullptr, out, MROWS, Vv, Dm);
}

// round 10
// speedup vs baseline: 1.2590x; 1.0265x over previous
#include <cuda_runtime.h>
#include <cuda_fp16.h>
#include <math.h>
#include <stdint.h>

#define Bz 2
#define Sq 1024
#define Dm 1024
#define Hh 16
#define Ll 6
#define Vv 50257
#define HDm 64
#define MROWS (Bz * Sq)
#define FFd (4 * Dm)

__device__ float  g_x[MROWS * Dm];              // fp32 residual stream
__device__ __half g_h[MROWS * Dm];
__device__ __half g_q[MROWS * Dm];
__device__ __half g_k[MROWS * Dm];
__device__ __half g_v[MROWS * Dm];
__device__ __half g_att[MROWS * Dm];
__device__ __half g_ff[MROWS * FFd];
__device__ __half g_wqt[Ll * Dm * Dm];
__device__ __half g_wkt[Ll * Dm * Dm];
__device__ __half g_wvt[Ll * Dm * Dm];
__device__ __half g_wot[Ll * Dm * Dm];
__device__ __half g_w1t[(size_t)Ll * Dm * FFd];
__device__ __half g_w2t[(size_t)Ll * FFd * Dm];
__device__ __half g_embh[(size_t)Vv * Dm];

__device__ __forceinline__ void cpasync16(void* sdst, const void* gsrc) {
    uint32_t d = (uint32_t)__cvta_generic_to_shared(sdst);
    asm volatile("cp.async.cg.shared.global [%0], [%1], 16;" :: "r"(d), "l"(gsrc));
}
__device__ __forceinline__ void mma_f16(float* c, const uint32_t* a, const uint32_t* b) {
    asm volatile(
        "mma.sync.aligned.m16n8k16.row.col.f32.f16.f16.f32 "
        "{%0,%1,%2,%3}, {%4,%5,%6,%7}, {%8,%9}, {%0,%1,%2,%3};"
        : "+f"(c[0]), "+f"(c[1]), "+f"(c[2]), "+f"(c[3])
        : "r"(a[0]), "r"(a[1]), "r"(a[2]), "r"(a[3]), "r"(b[0]), "r"(b[1]));
}
__device__ __forceinline__ void ldsm4(uint32_t* r, uint32_t addr) {
    asm volatile("ldmatrix.sync.aligned.m8n8.x4.shared.b16 {%0,%1,%2,%3}, [%4];"
                 : "=r"(r[0]), "=r"(r[1]), "=r"(r[2]), "=r"(r[3]) : "r"(addr));
}
__device__ __forceinline__ void store2(__half* C, size_t idx, float v0, float v1) {
    *reinterpret_cast<__half2*>(C + idx) = __floats2half2_rn(v0, v1);
}
__device__ __forceinline__ void store2(float* C, size_t idx, float v0, float v1) {
    float2 o; o.x = v0; o.y = v1;
    *reinterpret_cast<float2*>(C + idx) = o;
}

// ---------------------------------------------------------------------------
__global__ void embed_kernel(const int* __restrict__ tokens,
                             const float* __restrict__ tok_emb,
                             const float* __restrict__ pos_emb) {
    int idx = blockIdx.x * blockDim.x + threadIdx.x;
    if (idx >= MROWS * Dm / 4) return;
    int row = idx / (Dm / 4), c4 = idx % (Dm / 4), s = row % Sq;
    int tok = tokens[row];
    float4 te = reinterpret_cast<const float4*>(tok_emb + (size_t)tok * Dm)[c4];
    float4 pe = reinterpret_cast<const float4*>(pos_emb + (size_t)s * Dm)[c4];
    te.x += pe.x; te.y += pe.y; te.z += pe.z; te.w += pe.w;
    reinterpret_cast<float4*>(g_x)[idx] = te;
}

__global__ __launch_bounds__(256) void transpose4_h_kernel(
    const float* __restrict__ wq, const float* __restrict__ wk,
    const float* __restrict__ wv, const float* __restrict__ wo,
    __half* __restrict__ oq, __half* __restrict__ ok,
    __half* __restrict__ ov, __half* __restrict__ oo) {
    __shared__ float t[32][33];
    int which = blockIdx.z / Ll, l = blockIdx.z % Ll;
    const float* W = (which == 0) ? wq : (which == 1) ? wk : (which == 2) ? wv : wo;
    __half* O = (which == 0) ? oq : (which == 1) ? ok : (which == 2) ? ov : oo;
    const float* Wl = W + (size_t)l * Dm * Dm;
    __half* Ol = O + (size_t)l * Dm * Dm;
    int n0 = blockIdx.x * 32, k0 = blockIdx.y * 32;
    int tx = threadIdx.x & 31, ty = threadIdx.x >> 5;
#pragma unroll
    for (int i = 0; i < 32; i += 8)
        t[ty + i][tx] = Wl[(size_t)(k0 + ty + i) * Dm + n0 + tx];
    __syncthreads();
#pragma unroll
    for (int i = 0; i < 32; i += 8)
        Ol[(size_t)(n0 + ty + i) * Dm + k0 + tx] = __float2half(t[tx][ty + i]);
}

__global__ __launch_bounds__(256) void transpose_h_kernel(const float* __restrict__ W,
                                                          __half* __restrict__ WT, int K, int N) {
    __shared__ float t[32][33];
    const float* Wl = W + (size_t)blockIdx.z * K * N;
    __half* WTl = WT + (size_t)blockIdx.z * K * N;
    int n0 = blockIdx.x * 32, k0 = blockIdx.y * 32;
    int tx = threadIdx.x & 31, ty = threadIdx.x >> 5;
#pragma unroll
    for (int i = 0; i < 32; i += 8)
        t[ty + i][tx] = Wl[(size_t)(k0 + ty + i) * N + n0 + tx];
    __syncthreads();
#pragma unroll
    for (int i = 0; i < 32; i += 8)
        WTl[(size_t)(n0 + ty + i) * K + k0 + tx] = __float2half(t[tx][ty + i]);
}

__global__ __launch_bounds__(256) void emb_h_kernel(const float* __restrict__ E, __half* __restrict__ O) {
    size_t base = (size_t)blockIdx.x * Dm + threadIdx.x * 4;
    float4 v = *reinterpret_cast<const float4*>(E + base);
    __half2 h0 = __floats2half2_rn(v.x, v.y);
    __half2 h1 = __floats2half2_rn(v.z, v.w);
    uint2 u;
    u.x = *reinterpret_cast<uint32_t*>(&h0);
    u.y = *reinterpret_cast<uint32_t*>(&h1);
    *reinterpret_cast<uint2*>(O + base) = u;
}

__global__ __launch_bounds__(256) void ln_kernel(const float* __restrict__ x,
                                                 const float* __restrict__ gw,
                                                 const float* __restrict__ bw,
                                                 __half* __restrict__ out) {
    int row = blockIdx.x, tid = threadIdx.x;
    const float* xr = x + (size_t)row * Dm;
    float v[4], s = 0.f, s2 = 0.f;
#pragma unroll
    for (int i = 0; i < 4; i++) { v[i] = xr[tid + i * 256]; s += v[i]; s2 += v[i] * v[i]; }
#pragma unroll
    for (int o = 16; o > 0; o >>= 1) {
        s += __shfl_xor_sync(0xffffffffu, s, o);
        s2 += __shfl_xor_sync(0xffffffffu, s2, o);
    }
    __shared__ float ws[8], ws2[8];
    int w = tid >> 5, l = tid & 31;
    if (l == 0) { ws[w] = s; ws2[w] = s2; }
    __syncthreads();
    s = 0.f; s2 = 0.f;
#pragma unroll
    for (int i = 0; i < 8; i++) { s += ws[i]; s2 += ws2[i]; }
    float mean = s * (1.0f / Dm);
    float var = s2 * (1.0f / Dm) - mean * mean;
    float rstd = rsqrtf(var + 1e-5f);
    __half* orow = out + (size_t)row * Dm;
#pragma unroll
    for (int i = 0; i < 4; i++) {
        int col = tid + i * 256;
        orow[col] = __float2half((v[i] - mean) * rstd * gw[col] + bw[col]);
    }
}

// ---------------------------------------------------------------------------
// FP16 m16n8k16 GEMM with ldmatrix fragment loads.
// C = A[M,K] @ Bt[N,K]^T. CTA 128x128, BK=64 halves (128B SW128-swizzled rows),
// 3-stage cp.async, 256 threads, warp 64x32, 2 CTAs/SM.
// ---------------------------------------------------------------------------
#define STAGE_BYTES (2 * 128 * 128)     // 32768
#define SMEM_TOTAL (3 * STAGE_BYTES)    // 98304

template <int OP, bool VEC, bool SWAP, typename OutT>
__device__ __forceinline__ void gemm_body(const __half* __restrict__ A, const __half* __restrict__ Bt,
                                          const float* __restrict__ bias, const float* __restrict__ res,
                                          OutT* __restrict__ C, int M, int N, int K) {
    extern __shared__ char smem[];
    const int m0 = (SWAP ? blockIdx.x : blockIdx.y) * 128;
    const int n0 = (SWAP ? blockIdx.y : blockIdx.x) * 128;
    int tid = threadIdx.x, warp = tid >> 5, lane = tid & 31;
    int g = lane >> 2, tg = lane & 3;
    int wm = warp & 1, wn = warp >> 1;

    float acc[4][4][4];
#pragma unroll
    for (int mt = 0; mt < 4; mt++)
#pragma unroll
        for (int nt = 0; nt < 4; nt++)
#pragma unroll
            for (int i = 0; i < 4; i++) acc[mt][nt][i] = 0.f;

    const int KT = K / 64;
    uint32_t smemBase = (uint32_t)__cvta_generic_to_shared(smem);

    // ldmatrix per-lane row indices (constant across stages/kk):
    // A .x4: matrix i = lane>>3; row = wm*64 + mt*16 + ((lane>>3)&1)*8 + (lane&7),
    //        k-half sel = lane>>4
    int rowA_off = wm * 64 + ((lane >> 3) & 1) * 8 + (lane & 7);
    int aKsel = lane >> 4;           // 0/1 -> chunk +0/+1
    // B .x4 (load bb covers nt=2bb,2bb+1): row = wn*32 + (bb*2 + (lane>>4))*8 + (lane&7),
    //        k-half sel = (lane>>3)&1
    int rowB_off = wn * 32 + (lane >> 4) * 8 + (lane & 7);
    int bKsel = (lane >> 3) & 1;

    auto loadStage = [&](int stg) {
        char* base = smem + (stg % 3) * STAGE_BYTES;
        char* sa = base;
        char* sbf = base + 128 * 128;
        const __half* Ak = A + (size_t)m0 * K + stg * 64;
        const __half* Bk = Bt + stg * 64;
#pragma unroll
        for (int p = 0; p < 4; p++) {
            int id = tid + p * 256, r = id >> 3, c = id & 7;
            cpasync16(sa + r * 128 + ((c ^ (r & 7)) * 16), Ak + (size_t)r * K + c * 8);
        }
#pragma unroll
        for (int p = 0; p < 4; p++) {
            int id = tid + p * 256, r = id >> 3, c = id & 7;
            int n = n0 + r; if (n >= N) n = N - 1;
            cpasync16(sbf + r * 128 + ((c ^ (r & 7)) * 16), Bk + (size_t)n * K + c * 8);
        }
        asm volatile("cp.async.commit_group;");
    };

    loadStage(0);
    loadStage(1);

    for (int j = 0; j < KT; j++) {
        if (j + 1 < KT) asm volatile("cp.async.wait_group 1;");
        else            asm volatile("cp.async.wait_group 0;");
        __syncthreads();
        if (j + 2 < KT) loadStage(j + 2);

        uint32_t aBase = smemBase + (j % 3) * STAGE_BYTES;
        uint32_t bBase = aBase + 128 * 128;

#pragma unroll
        for (int kk = 0; kk < 4; kk++) {
            uint32_t afr[4][4];
#pragma unroll
            for (int mt = 0; mt < 4; mt++) {
                int row = rowA_off + mt * 16;
                int ch = 2 * kk + aKsel;
                uint32_t addr = aBase + row * 128 + (((ch ^ (row & 7)) & 7) << 4);
                ldsm4(afr[mt], addr);
            }
            uint32_t bfr[4][2];
#pragma unroll
            for (int bb = 0; bb < 2; bb++) {
                int row = rowB_off + bb * 16;
                int ch = 2 * kk + bKsel;
                uint32_t addr = bBase + row * 128 + (((ch ^ (row & 7)) & 7) << 4);
                uint32_t t[4];
                ldsm4(t, addr);
                bfr[bb * 2 + 0][0] = t[0];
                bfr[bb * 2 + 0][1] = t[1];
                bfr[bb * 2 + 1][0] = t[2];
                bfr[bb * 2 + 1][1] = t[3];
            }
#pragma unroll
            for (int mt = 0; mt < 4; mt++)
#pragma unroll
                for (int nt = 0; nt < 4; nt++)
                    mma_f16(acc[mt][nt], afr[mt], bfr[nt]);
        }
    }

#pragma unroll
    for (int mt = 0; mt < 4; mt++) {
#pragma unroll
        for (int half = 0; half < 2; half++) {
            int m = m0 + wm * 64 + mt * 16 + g + half * 8;
#pragma unroll
            for (int nt = 0; nt < 4; nt++) {
                int col = n0 + wn * 32 + nt * 8 + tg * 2;
                float v0 = acc[mt][nt][half * 2 + 0];
                float v1 = acc[mt][nt][half * 2 + 1];
                if (OP == 2 || OP == 3) { v0 += bias[col]; v1 += bias[col + 1]; }
                if (OP == 2) {
                    v0 = 0.5f * v0 * (1.0f + erff(v0 * 0.70710678118654752f));
                    v1 = 0.5f * v1 * (1.0f + erff(v1 * 0.70710678118654752f));
                }
                if (OP == 1 || OP == 3) {
                    float2 r = *reinterpret_cast<const float2*>(res + (size_t)m * N + col);
                    v0 += r.x; v1 += r.y;
                }
                if (VEC) {
                    store2(C, (size_t)m * N + col, v0, v1);
                } else {
                    if (col < N)     C[(size_t)m * N + col]     = (OutT)v0;
                    if (col + 1 < N) C[(size_t)m * N + col + 1] = (OutT)v1;
                }
            }
        }
    }
}

template <int OP, bool VEC, bool SWAP, typename OutT>
__global__ __launch_bounds__(256, 2) void gemm_kernel(const __half* __restrict__ A, const __half* __restrict__ Bt,
                                                      const float* __restrict__ bias, const float* __restrict__ res,
                                                      OutT* __restrict__ C, int M, int N, int K) {
    gemm_body<OP, VEC, SWAP, OutT>(A, Bt, bias, res, C, M, N, K);
}

__global__ __launch_bounds__(256, 2) void qkv_kernel(const __half* __restrict__ A, const __half* __restrict__ Wqt,
                                                     const __half* __restrict__ Wkt, const __half* __restrict__ Wvt,
                                                     __half* __restrict__ Qo, __half* __restrict__ Ko,
                                                     __half* __restrict__ Vo) {
    const __half* Bt = (blockIdx.z == 0) ? Wqt : (blockIdx.z == 1 ? Wkt : Wvt);
    __half* C = (blockIdx.z == 0) ? Qo : (blockIdx.z == 1 ? Ko : Vo);
    gemm_body<0, true, false, __half>(A, Bt, nullptr, nullptr, C, MROWS, Dm, Dm);
}

// ---------------------------------------------------------------------------
__global__ __launch_bounds__(256) void attn_kernel(const __half* __restrict__ Qg,
                                                   const __half* __restrict__ Kg,
                                                   const __half* __restrict__ Vg,
                                                   __half* __restrict__ Og) {
    __shared__ float Qs[64][64];
    __shared__ float Ks[64][64];
    __shared__ float Vs[64][64];
    int b = blockIdx.z, h = blockIdx.y, qi = blockIdx.x;
    int tid = threadIdx.x;
    for (int t = tid; t < 512; t += 256) {
        int r = t >> 3, c8 = t & 7;
        const __half2* src = reinterpret_cast<const __half2*>(
            Qg + ((size_t)(b * Sq + qi * 64 + r) * Dm) + h * HDm + c8 * 8);
#pragma unroll
        for (int i = 0; i < 4; i++) {
            float2 f = __half22float2(src[i]);
            Qs[r][c8 * 8 + 2 * i] = f.x;
            Qs[r][c8 * 8 + 2 * i + 1] = f.y;
        }
    }
    int q = tid >> 2, c = tid & 3;
    float m_i = -INFINITY, l_i = 0.f;
    float o[16];
#pragma unroll
    for (int d = 0; d < 16; d++) o[d] = 0.f;
    const float scale = 0.125f;
    int qg = qi * 64 + q;

    for (int j = 0; j <= qi; j++) {
        __syncthreads();
        for (int t = tid; t < 512; t += 256) {
            int r = t >> 3, c8 = t & 7;
            size_t base = ((size_t)(b * Sq + j * 64 + r) * Dm) + h * HDm + c8 * 8;
            const __half2* ks = reinterpret_cast<const __half2*>(Kg + base);
            const __half2* vs = reinterpret_cast<const __half2*>(Vg + base);
#pragma unroll
            for (int i = 0; i < 4; i++) {
                float2 fk = __half22float2(ks[i]);
                float2 fv = __half22float2(vs[i]);
                Ks[r][c8 * 8 + 2 * i] = fk.x; Ks[r][c8 * 8 + 2 * i + 1] = fk.y;
                Vs[r][c8 * 8 + 2 * i] = fv.x; Vs[r][c8 * 8 + 2 * i + 1] = fv.y;
            }
        }
        __syncthreads();
        float s[16];
#pragma unroll
        for (int kk = 0; kk < 16; kk++) s[kk] = 0.f;
#pragma unroll 4
        for (int kd4 = 0; kd4 < 16; kd4++) {
            float4 qv = *reinterpret_cast<const float4*>(&Qs[q][kd4 * 4]);
#pragma unroll
            for (int kk = 0; kk < 16; kk++) {
                float4 kv = *reinterpret_cast<const float4*>(&Ks[c * 16 + kk][kd4 * 4]);
                s[kk] += qv.x * kv.x + qv.y * kv.y + qv.z * kv.z + qv.w * kv.w;
            }
        }
#pragma unroll
        for (int kk = 0; kk < 16; kk++) {
            int kg = j * 64 + c * 16 + kk;
            s[kk] = (kg <= qg) ? s[kk] * scale : -INFINITY;
        }
        float mloc = s[0];
#pragma unroll
        for (int kk = 1; kk < 16; kk++) mloc = fmaxf(mloc, s[kk]);
        mloc = fmaxf(mloc, __shfl_xor_sync(0xffffffffu, mloc, 1, 4));
        mloc = fmaxf(mloc, __shfl_xor_sync(0xffffffffu, mloc, 2, 4));
        float mnew = fmaxf(m_i, mloc);
        float alpha = expf(m_i - mnew);
        float p[16], lloc = 0.f;
#pragma unroll
        for (int kk = 0; kk < 16; kk++) { p[kk] = expf(s[kk] - mnew); lloc += p[kk]; }
        lloc += __shfl_xor_sync(0xffffffffu, lloc, 1, 4);
        lloc += __shfl_xor_sync(0xffffffffu, lloc, 2, 4);
        l_i = l_i * alpha + lloc;
        m_i = mnew;
#pragma unroll
        for (int d = 0; d < 16; d++) o[d] *= alpha;
#pragma unroll
        for (int src = 0; src < 4; src++) {
#pragma unroll
            for (int kk = 0; kk < 16; kk++) {
                float pv = __shfl_sync(0xffffffffu, p[kk], src, 4);
                int key = src * 16 + kk;
#pragma unroll
                for (int d4 = 0; d4 < 4; d4++) {
                    float4 vv = *reinterpret_cast<const float4*>(&Vs[key][c * 16 + d4 * 4]);
                    o[d4 * 4 + 0] += pv * vv.x;
                    o[d4 * 4 + 1] += pv * vv.y;
                    o[d4 * 4 + 2] += pv * vv.z;
                    o[d4 * 4 + 3] += pv * vv.w;
                }
            }
        }
    }
    float inv = 1.0f / l_i;
    __half* op = Og + ((size_t)(b * Sq + qi * 64 + q) * Dm) + h * HDm + c * 16;
#pragma unroll
    for (int d2 = 0; d2 < 8; d2++) {
        *reinterpret_cast<__half2*>(op + d2 * 2) =
            __floats2half2_rn(o[d2 * 2] * inv, o[d2 * 2 + 1] * inv);
    }
}

// ---------------------------------------------------------------------------
extern "C" void kernel_launch(void* const* d_in, const int* in_sizes, int n_in,
                              void* d_out, int out_size) {
    const int*   tokens  = (const int*)d_in[0];
    const float* tok_emb = (const float*)d_in[1];
    const float* pos_emb = (const float*)d_in[2];
    const float* ln1_g = (const float*)d_in[3];
    const float* ln1_b = (const float*)d_in[4];
    const float* wq = (const float*)d_in[5];
    const float* wk = (const float*)d_in[6];
    const float* wv = (const float*)d_in[7];
    const float* wo = (const float*)d_in[8];
    const float* ln2_g = (const float*)d_in[9];
    const float* ln2_b = (const float*)d_in[10];
    const float* w1 = (const float*)d_in[11];
    const float* b1 = (const float*)d_in[12];
    const float* w2 = (const float*)d_in[13];
    const float* b2 = (const float*)d_in[14];
    const float* lnf_g = (const float*)d_in[15];
    const float* lnf_b = (const float*)d_in[16];
    float* out = (float*)d_out;

    float *px;
    __half *ph, *pq, *pk, *pv, *pa, *pf, *pwqt, *pwkt, *pwvt, *pwot, *pw1t, *pw2t, *pembh;
    cudaGetSymbolAddress((void**)&px, g_x);
    cudaGetSymbolAddress((void**)&ph, g_h);
    cudaGetSymbolAddress((void**)&pq, g_q);
    cudaGetSymbolAddress((void**)&pk, g_k);
    cudaGetSymbolAddress((void**)&pv, g_v);
    cudaGetSymbolAddress((void**)&pa, g_att);
    cudaGetSymbolAddress((void**)&pf, g_ff);
    cudaGetSymbolAddress((void**)&pwqt, g_wqt);
    cudaGetSymbolAddress((void**)&pwkt, g_wkt);
    cudaGetSymbolAddress((void**)&pwvt, g_wvt);
    cudaGetSymbolAddress((void**)&pwot, g_wot);
    cudaGetSymbolAddress((void**)&pw1t, g_w1t);
    cudaGetSymbolAddress((void**)&pw2t, g_w2t);
    cudaGetSymbolAddress((void**)&pembh, g_embh);

    cudaFuncSetAttribute((const void*)gemm_kernel<0, false, true, float>,  cudaFuncAttributeMaxDynamicSharedMemorySize, SMEM_TOTAL);
    cudaFuncSetAttribute((const void*)gemm_kernel<1, true, false, float>,  cudaFuncAttributeMaxDynamicSharedMemorySize, SMEM_TOTAL);
    cudaFuncSetAttribute((const void*)gemm_kernel<2, true, false, __half>, cudaFuncAttributeMaxDynamicSharedMemorySize, SMEM_TOTAL);
    cudaFuncSetAttribute((const void*)gemm_kernel<3, true, false, float>,  cudaFuncAttributeMaxDynamicSharedMemorySize, SMEM_TOTAL);
    cudaFuncSetAttribute((const void*)qkv_kernel,                          cudaFuncAttributeMaxDynamicSharedMemorySize, SMEM_TOTAL);

    dim3 gD(Dm / 128, MROWS / 128);
    dim3 gQKV(Dm / 128, MROWS / 128, 3);
    dim3 gFF(FFd / 128, MROWS / 128);
    dim3 gAttn(Sq / 64, Hh, Bz);

    // Launch order: #0 t4, #1 embed, #2 ln1(l0), #3 qkv(l0)  <- ncu captures #3
    dim3 gT4(Dm / 32, Dm / 32, 4 * Ll);
    transpose4_h_kernel<<<gT4, 256>>>(wq, wk, wv, wo, pwqt, pwkt, pwvt, pwot);
    embed_kernel<<<MROWS * Dm / 4 / 256, 256>>>(tokens, tok_emb, pos_emb);
    ln_kernel<<<MROWS, 256>>>(px, ln1_g, ln1_b, ph);
    qkv_kernel<<<gQKV, 256, SMEM_TOTAL>>>(ph, pwqt, pwkt, pwvt, pq, pk, pv);

    // remaining prep (independent of layer-0 attention path)
    dim3 gT1(FFd / 32, Dm / 32, Ll);
    transpose_h_kernel<<<gT1, 256>>>(w1, pw1t, Dm, FFd);
    dim3 gT2(Dm / 32, FFd / 32, Ll);
    transpose_h_kernel<<<gT2, 256>>>(w2, pw2t, FFd, Dm);
    emb_h_kernel<<<Vv, 256>>>(tok_emb, pembh);

    for (int l = 0; l < Ll; l++) {
        const __half* lWqt = pwqt + (size_t)l * Dm * Dm;
        const __half* lWkt = pwkt + (size_t)l * Dm * Dm;
        const __half* lWvt = pwvt + (size_t)l * Dm * Dm;
        const __half* lWot = pwot + (size_t)l * Dm * Dm;
        const __half* lW1t = pw1t + (size_t)l * Dm * FFd;
        const __half* lW2t = pw2t + (size_t)l * FFd * Dm;
        const float* lB1 = b1 + (size_t)l * FFd;
        const float* lB2 = b2 + (size_t)l * Dm;

        if (l > 0) {
            ln_kernel<<<MROWS, 256>>>(px, ln1_g + (size_t)l * Dm, ln1_b + (size_t)l * Dm, ph);
            qkv_kernel<<<gQKV, 256, SMEM_TOTAL>>>(ph, lWqt, lWkt, lWvt, pq, pk, pv);
        }
        attn_kernel<<<gAttn, 256>>>(pq, pk, pv, pa);
        gemm_kernel<1, true, false, float><<<gD, 256, SMEM_TOTAL>>>(pa, lWot, nullptr, px, px, MROWS, Dm, Dm);
        ln_kernel<<<MROWS, 256>>>(px, ln2_g + (size_t)l * Dm, ln2_b + (size_t)l * Dm, ph);
        gemm_kernel<2, true, false, __half><<<gFF, 256, SMEM_TOTAL>>>(ph, lW1t, lB1, nullptr, pf, MROWS, FFd, Dm);
        gemm_kernel<3, true, false, float><<<gD, 256, SMEM_TOTAL>>>(pf, lW2t, lB2, px, px, MROWS, Dm, FFd);
    }

    ln_kernel<<<MROWS, 256>>>(px, lnf_g, lnf_b, ph);
    dim3 gLog(MROWS / 128, (Vv + 127) / 128);
    gemm_kernel<0, false, true, float><<<gLog, 256, SMEM_TOTAL>>>(ph, pembh, nullptr, nullptr, out, MROWS, Vv, Dm);
}

// round 11
// speedup vs baseline: 4.1942x; 3.3313x over previous
#include <cuda_runtime.h>
#include <cuda_fp16.h>
#include <math.h>
#include <stdint.h>

#define Bz 2
#define Sq 1024
#define Dm 1024
#define Hh 16
#define Ll 6
#define Vv 50257
#define HDm 64
#define MROWS (Bz * Sq)
#define FFd (4 * Dm)

__device__ float  g_x[MROWS * Dm];              // fp32 residual stream
__device__ __half g_h[MROWS * Dm];
__device__ __half g_q[MROWS * Dm];
__device__ __half g_k[MROWS * Dm];
__device__ __half g_v[MROWS * Dm];
__device__ __half g_att[MROWS * Dm];
__device__ __half g_ff[MROWS * FFd];
__device__ __half g_wqt[Ll * Dm * Dm];
__device__ __half g_wkt[Ll * Dm * Dm];
__device__ __half g_wvt[Ll * Dm * Dm];
__device__ __half g_wot[Ll * Dm * Dm];
__device__ __half g_w1t[(size_t)Ll * Dm * FFd];
__device__ __half g_w2t[(size_t)Ll * FFd * Dm];
__device__ __half g_embh[(size_t)Vv * Dm];

__device__ __forceinline__ void cpasync16(void* sdst, const void* gsrc) {
    uint32_t d = (uint32_t)__cvta_generic_to_shared(sdst);
    asm volatile("cp.async.cg.shared.global [%0], [%1], 16;" :: "r"(d), "l"(gsrc));
}
__device__ __forceinline__ void mma_f16(float* c, const uint32_t* a, const uint32_t* b) {
    asm volatile(
        "mma.sync.aligned.m16n8k16.row.col.f32.f16.f16.f32 "
        "{%0,%1,%2,%3}, {%4,%5,%6,%7}, {%8,%9}, {%0,%1,%2,%3};"
        : "+f"(c[0]), "+f"(c[1]), "+f"(c[2]), "+f"(c[3])
        : "r"(a[0]), "r"(a[1]), "r"(a[2]), "r"(a[3]), "r"(b[0]), "r"(b[1]));
}
__device__ __forceinline__ void ldsm4(uint32_t* r, uint32_t addr) {
    asm volatile("ldmatrix.sync.aligned.m8n8.x4.shared.b16 {%0,%1,%2,%3}, [%4];"
                 : "=r"(r[0]), "=r"(r[1]), "=r"(r[2]), "=r"(r[3]) : "r"(addr));
}
__device__ __forceinline__ void ldsm4t(uint32_t* r, uint32_t addr) {
    asm volatile("ldmatrix.sync.aligned.m8n8.x4.trans.shared.b16 {%0,%1,%2,%3}, [%4];"
                 : "=r"(r[0]), "=r"(r[1]), "=r"(r[2]), "=r"(r[3]) : "r"(addr));
}
__device__ __forceinline__ void store2(__half* C, size_t idx, float v0, float v1) {
    *reinterpret_cast<__half2*>(C + idx) = __floats2half2_rn(v0, v1);
}
__device__ __forceinline__ void store2(float* C, size_t idx, float v0, float v1) {
    float2 o; o.x = v0; o.y = v1;
    *reinterpret_cast<float2*>(C + idx) = o;
}

// ---------------------------------------------------------------------------
// Fused embedding + LayerNorm(layer 0): writes g_x (fp32) and g_h (half LN)
// ---------------------------------------------------------------------------
__global__ __launch_bounds__(256) void embed_ln_kernel(const int* __restrict__ tokens,
                                                       const float* __restrict__ tok_emb,
                                                       const float* __restrict__ pos_emb,
                                                       const float* __restrict__ gw,
                                                       const float* __restrict__ bw) {
    int row = blockIdx.x, tid = threadIdx.x;
    int s = row % Sq;
    int tok = tokens[row];
    const float* te = tok_emb + (size_t)tok * Dm;
    const float* pe = pos_emb + (size_t)s * Dm;
    float v[4], sm = 0.f, s2 = 0.f;
#pragma unroll
    for (int i = 0; i < 4; i++) {
        int col = tid + i * 256;
        v[i] = te[col] + pe[col];
        g_x[(size_t)row * Dm + col] = v[i];
        sm += v[i]; s2 += v[i] * v[i];
    }
#pragma unroll
    for (int o = 16; o > 0; o >>= 1) {
        sm += __shfl_xor_sync(0xffffffffu, sm, o);
        s2 += __shfl_xor_sync(0xffffffffu, s2, o);
    }
    __shared__ float ws[8], ws2[8];
    int w = tid >> 5, l = tid & 31;
    if (l == 0) { ws[w] = sm; ws2[w] = s2; }
    __syncthreads();
    sm = 0.f; s2 = 0.f;
#pragma unroll
    for (int i = 0; i < 8; i++) { sm += ws[i]; s2 += ws2[i]; }
    float mean = sm * (1.0f / Dm);
    float var = s2 * (1.0f / Dm) - mean * mean;
    float rstd = rsqrtf(var + 1e-5f);
#pragma unroll
    for (int i = 0; i < 4; i++) {
        int col = tid + i * 256;
        g_h[(size_t)row * Dm + col] = __float2half((v[i] - mean) * rstd * gw[col] + bw[col]);
    }
}

__global__ __launch_bounds__(256) void transpose4_h_kernel(
    const float* __restrict__ wq, const float* __restrict__ wk,
    const float* __restrict__ wv, const float* __restrict__ wo,
    __half* __restrict__ oq, __half* __restrict__ ok,
    __half* __restrict__ ov, __half* __restrict__ oo) {
    __shared__ float t[32][33];
    int which = blockIdx.z / Ll, l = blockIdx.z % Ll;
    const float* W = (which == 0) ? wq : (which == 1) ? wk : (which == 2) ? wv : wo;
    __half* O = (which == 0) ? oq : (which == 1) ? ok : (which == 2) ? ov : oo;
    const float* Wl = W + (size_t)l * Dm * Dm;
    __half* Ol = O + (size_t)l * Dm * Dm;
    int n0 = blockIdx.x * 32, k0 = blockIdx.y * 32;
    int tx = threadIdx.x & 31, ty = threadIdx.x >> 5;
#pragma unroll
    for (int i = 0; i < 32; i += 8)
        t[ty + i][tx] = Wl[(size_t)(k0 + ty + i) * Dm + n0 + tx];
    __syncthreads();
#pragma unroll
    for (int i = 0; i < 32; i += 8)
        Ol[(size_t)(n0 + ty + i) * Dm + k0 + tx] = __float2half(t[tx][ty + i]);
}

__global__ __launch_bounds__(256) void transpose_h_kernel(const float* __restrict__ W,
                                                          __half* __restrict__ WT, int K, int N) {
    __shared__ float t[32][33];
    const float* Wl = W + (size_t)blockIdx.z * K * N;
    __half* WTl = WT + (size_t)blockIdx.z * K * N;
    int n0 = blockIdx.x * 32, k0 = blockIdx.y * 32;
    int tx = threadIdx.x & 31, ty = threadIdx.x >> 5;
#pragma unroll
    for (int i = 0; i < 32; i += 8)
        t[ty + i][tx] = Wl[(size_t)(k0 + ty + i) * N + n0 + tx];
    __syncthreads();
#pragma unroll
    for (int i = 0; i < 32; i += 8)
        WTl[(size_t)(n0 + ty + i) * K + k0 + tx] = __float2half(t[tx][ty + i]);
}

__global__ __launch_bounds__(256) void emb_h_kernel(const float* __restrict__ E, __half* __restrict__ O) {
    size_t base = (size_t)blockIdx.x * Dm + threadIdx.x * 4;
    float4 v = *reinterpret_cast<const float4*>(E + base);
    __half2 h0 = __floats2half2_rn(v.x, v.y);
    __half2 h1 = __floats2half2_rn(v.z, v.w);
    uint2 u;
    u.x = *reinterpret_cast<uint32_t*>(&h0);
    u.y = *reinterpret_cast<uint32_t*>(&h1);
    *reinterpret_cast<uint2*>(O + base) = u;
}

__global__ __launch_bounds__(256) void ln_kernel(const float* __restrict__ x,
                                                 const float* __restrict__ gw,
                                                 const float* __restrict__ bw,
                                                 __half* __restrict__ out) {
    int row = blockIdx.x, tid = threadIdx.x;
    const float* xr = x + (size_t)row * Dm;
    float v[4], s = 0.f, s2 = 0.f;
#pragma unroll
    for (int i = 0; i < 4; i++) { v[i] = xr[tid + i * 256]; s += v[i]; s2 += v[i] * v[i]; }
#pragma unroll
    for (int o = 16; o > 0; o >>= 1) {
        s += __shfl_xor_sync(0xffffffffu, s, o);
        s2 += __shfl_xor_sync(0xffffffffu, s2, o);
    }
    __shared__ float ws[8], ws2[8];
    int w = tid >> 5, l = tid & 31;
    if (l == 0) { ws[w] = s; ws2[w] = s2; }
    __syncthreads();
    s = 0.f; s2 = 0.f;
#pragma unroll
    for (int i = 0; i < 8; i++) { s += ws[i]; s2 += ws2[i]; }
    float mean = s * (1.0f / Dm);
    float var = s2 * (1.0f / Dm) - mean * mean;
    float rstd = rsqrtf(var + 1e-5f);
    __half* orow = out + (size_t)row * Dm;
#pragma unroll
    for (int i = 0; i < 4; i++) {
        int col = tid + i * 256;
        orow[col] = __float2half((v[i] - mean) * rstd * gw[col] + bw[col]);
    }
}

// ---------------------------------------------------------------------------
// FP16 m16n8k16 GEMM with ldmatrix (unchanged from round 10).
// ---------------------------------------------------------------------------
#define STAGE_BYTES (2 * 128 * 128)
#define SMEM_TOTAL (3 * STAGE_BYTES)

template <int OP, bool VEC, bool SWAP, typename OutT>
__device__ __forceinline__ void gemm_body(const __half* __restrict__ A, const __half* __restrict__ Bt,
                                          const float* __restrict__ bias, const float* __restrict__ res,
                                          OutT* __restrict__ C, int M, int N, int K) {
    extern __shared__ char smem[];
    const int m0 = (SWAP ? blockIdx.x : blockIdx.y) * 128;
    const int n0 = (SWAP ? blockIdx.y : blockIdx.x) * 128;
    int tid = threadIdx.x, warp = tid >> 5, lane = tid & 31;
    int g = lane >> 2, tg = lane & 3;
    int wm = warp & 1, wn = warp >> 1;

    float acc[4][4][4];
#pragma unroll
    for (int mt = 0; mt < 4; mt++)
#pragma unroll
        for (int nt = 0; nt < 4; nt++)
#pragma unroll
            for (int i = 0; i < 4; i++) acc[mt][nt][i] = 0.f;

    const int KT = K / 64;
    uint32_t smemBase = (uint32_t)__cvta_generic_to_shared(smem);

    int rowA_off = wm * 64 + ((lane >> 3) & 1) * 8 + (lane & 7);
    int aKsel = lane >> 4;
    int rowB_off = wn * 32 + (lane >> 4) * 8 + (lane & 7);
    int bKsel = (lane >> 3) & 1;

    auto loadStage = [&](int stg) {
        char* base = smem + (stg % 3) * STAGE_BYTES;
        char* sa = base;
        char* sbf = base + 128 * 128;
        const __half* Ak = A + (size_t)m0 * K + stg * 64;
        const __half* Bk = Bt + stg * 64;
#pragma unroll
        for (int p = 0; p < 4; p++) {
            int id = tid + p * 256, r = id >> 3, c = id & 7;
            cpasync16(sa + r * 128 + ((c ^ (r & 7)) * 16), Ak + (size_t)r * K + c * 8);
        }
#pragma unroll
        for (int p = 0; p < 4; p++) {
            int id = tid + p * 256, r = id >> 3, c = id & 7;
            int n = n0 + r; if (n >= N) n = N - 1;
            cpasync16(sbf + r * 128 + ((c ^ (r & 7)) * 16), Bk + (size_t)n * K + c * 8);
        }
        asm volatile("cp.async.commit_group;");
    };

    loadStage(0);
    loadStage(1);

    for (int j = 0; j < KT; j++) {
        if (j + 1 < KT) asm volatile("cp.async.wait_group 1;");
        else            asm volatile("cp.async.wait_group 0;");
        __syncthreads();
        if (j + 2 < KT) loadStage(j + 2);

        uint32_t aBase = smemBase + (j % 3) * STAGE_BYTES;
        uint32_t bBase = aBase + 128 * 128;

#pragma unroll
        for (int kk = 0; kk < 4; kk++) {
            uint32_t afr[4][4];
#pragma unroll
            for (int mt = 0; mt < 4; mt++) {
                int row = rowA_off + mt * 16;
                int ch = 2 * kk + aKsel;
                uint32_t addr = aBase + row * 128 + (((ch ^ (row & 7)) & 7) << 4);
                ldsm4(afr[mt], addr);
            }
            uint32_t bfr[4][2];
#pragma unroll
            for (int bb = 0; bb < 2; bb++) {
                int row = rowB_off + bb * 16;
                int ch = 2 * kk + bKsel;
                uint32_t addr = bBase + row * 128 + (((ch ^ (row & 7)) & 7) << 4);
                uint32_t t[4];
                ldsm4(t, addr);
                bfr[bb * 2 + 0][0] = t[0];
                bfr[bb * 2 + 0][1] = t[1];
                bfr[bb * 2 + 1][0] = t[2];
                bfr[bb * 2 + 1][1] = t[3];
            }
#pragma unroll
            for (int mt = 0; mt < 4; mt++)
#pragma unroll
                for (int nt = 0; nt < 4; nt++)
                    mma_f16(acc[mt][nt], afr[mt], bfr[nt]);
        }
    }

#pragma unroll
    for (int mt = 0; mt < 4; mt++) {
#pragma unroll
        for (int half = 0; half < 2; half++) {
            int m = m0 + wm * 64 + mt * 16 + g + half * 8;
#pragma unroll
            for (int nt = 0; nt < 4; nt++) {
                int col = n0 + wn * 32 + nt * 8 + tg * 2;
                float v0 = acc[mt][nt][half * 2 + 0];
                float v1 = acc[mt][nt][half * 2 + 1];
                if (OP == 2 || OP == 3) { v0 += bias[col]; v1 += bias[col + 1]; }
                if (OP == 2) {
                    v0 = 0.5f * v0 * (1.0f + erff(v0 * 0.70710678118654752f));
                    v1 = 0.5f * v1 * (1.0f + erff(v1 * 0.70710678118654752f));
                }
                if (OP == 1 || OP == 3) {
                    float2 r = *reinterpret_cast<const float2*>(res + (size_t)m * N + col);
                    v0 += r.x; v1 += r.y;
                }
                if (VEC) {
                    store2(C, (size_t)m * N + col, v0, v1);
                } else {
                    if (col < N)     C[(size_t)m * N + col]     = (OutT)v0;
                    if (col + 1 < N) C[(size_t)m * N + col + 1] = (OutT)v1;
                }
            }
        }
    }
}

template <int OP, bool VEC, bool SWAP, typename OutT>
__global__ __launch_bounds__(256, 2) void gemm_kernel(const __half* __restrict__ A, const __half* __restrict__ Bt,
                                                      const float* __restrict__ bias, const float* __restrict__ res,
                                                      OutT* __restrict__ C, int M, int N, int K) {
    gemm_body<OP, VEC, SWAP, OutT>(A, Bt, bias, res, C, M, N, K);
}

__global__ __launch_bounds__(256, 2) void qkv_kernel(const __half* __restrict__ A, const __half* __restrict__ Wqt,
                                                     const __half* __restrict__ Wkt, const __half* __restrict__ Wvt,
                                                     __half* __restrict__ Qo, __half* __restrict__ Ko,
                                                     __half* __restrict__ Vo) {
    const __half* Bt = (blockIdx.z == 0) ? Wqt : (blockIdx.z == 1 ? Wkt : Wvt);
    __half* C = (blockIdx.z == 0) ? Qo : (blockIdx.z == 1 ? Ko : Vo);
    gemm_body<0, true, false, __half>(A, Bt, nullptr, nullptr, C, MROWS, Dm, Dm);
}

// ---------------------------------------------------------------------------
// Tensor-core flash attention.
// grid (Sq/64, Hh, Bz), 128 threads (4 warps), warp = 16 query rows.
// Q tile 64x64 half smem (SW128 swizzle), K/V double-buffered cp.async tiles.
// S = Q@K^T (m16n8k16, fp32 acc), online softmax in regs, O += P@V with
// P remapped accumulator->A-fragment and V loaded via ldmatrix.trans.
// ---------------------------------------------------------------------------
__global__ __launch_bounds__(128) void attn_kernel(const __half* __restrict__ Qg,
                                                   const __half* __restrict__ Kg,
                                                   const __half* __restrict__ Vg,
                                                   __half* __restrict__ Og) {
    __shared__ __align__(128) __half Qs[64 * 64];
    __shared__ __align__(128) __half Ks[2][64 * 64];
    __shared__ __align__(128) __half Vs[2][64 * 64];

    int b = blockIdx.z, h = blockIdx.y, qi = blockIdx.x;
    int tid = threadIdx.x, warp = tid >> 5, lane = tid & 31;
    int g = lane >> 2, tg = lane & 3;

    uint32_t qBase = (uint32_t)__cvta_generic_to_shared(Qs);
    uint32_t kBase0 = (uint32_t)__cvta_generic_to_shared(Ks[0]);
    uint32_t vBase0 = (uint32_t)__cvta_generic_to_shared(Vs[0]);

    // ---- load Q tile + KV tile 0 ----
    {
        const __half* Qp = Qg + ((size_t)(b * Sq + qi * 64) * Dm) + h * HDm;
#pragma unroll
        for (int p = 0; p < 4; p++) {
            int id = tid + p * 128, r = id >> 3, c = id & 7;
            cpasync16((char*)Qs + r * 128 + ((c ^ (r & 7)) * 16), Qp + (size_t)r * Dm + c * 8);
        }
        const __half* Kp = Kg + ((size_t)(b * Sq) * Dm) + h * HDm;
        const __half* Vp = Vg + ((size_t)(b * Sq) * Dm) + h * HDm;
#pragma unroll
        for (int p = 0; p < 4; p++) {
            int id = tid + p * 128, r = id >> 3, c = id & 7;
            cpasync16((char*)Ks[0] + r * 128 + ((c ^ (r & 7)) * 16), Kp + (size_t)r * Dm + c * 8);
            cpasync16((char*)Vs[0] + r * 128 + ((c ^ (r & 7)) * 16), Vp + (size_t)r * Dm + c * 8);
        }
        asm volatile("cp.async.commit_group;");
    }
    asm volatile("cp.async.wait_group 0;");
    __syncthreads();

    // ---- Q fragments (hoisted; Qs never rewritten) ----
    uint32_t qfr[4][4];
    {
        int rowA = warp * 16 + ((lane >> 3) & 1) * 8 + (lane & 7);
        int aKsel = lane >> 4;
#pragma unroll
        for (int kk = 0; kk < 4; kk++) {
            int ch = 2 * kk + aKsel;
            ldsm4(qfr[kk], qBase + rowA * 128 + (((ch ^ (rowA & 7)) & 7) << 4));
        }
    }

    float m0 = -INFINITY, m1 = -INFINITY, l0 = 0.f, l1 = 0.f;
    float o[8][4];
#pragma unroll
    for (int nt = 0; nt < 8; nt++)
#pragma unroll
        for (int i = 0; i < 4; i++) o[nt][i] = 0.f;

    const float scale = 0.125f;
    int rowBK_off = (lane >> 4) * 8 + (lane & 7);   // K b-frag row offset
    int bKsel = (lane >> 3) & 1;
    int rowV_off = ((lane >> 3) & 1) * 8 + (lane & 7);  // V trans row offset
    int vNsel = lane >> 4;
    int rq0 = warp * 16 + g;                         // query row in tile (lane rows rq0, rq0+8)

    for (int j = 0; j <= qi; j++) {
        int buf = j & 1;
        __syncthreads();   // all warps done reading buf^1 (iter j-1) before overwrite
        bool pref = (j + 1 <= qi);
        if (pref) {
            int nb = buf ^ 1;
            const __half* Kp = Kg + ((size_t)(b * Sq + (j + 1) * 64) * Dm) + h * HDm;
            const __half* Vp = Vg + ((size_t)(b * Sq + (j + 1) * 64) * Dm) + h * HDm;
#pragma unroll
            for (int p = 0; p < 4; p++) {
                int id = tid + p * 128, r = id >> 3, c = id & 7;
                cpasync16((char*)Ks[nb] + r * 128 + ((c ^ (r & 7)) * 16), Kp + (size_t)r * Dm + c * 8);
                cpasync16((char*)Vs[nb] + r * 128 + ((c ^ (r & 7)) * 16), Vp + (size_t)r * Dm + c * 8);
            }
            asm volatile("cp.async.commit_group;");
            asm volatile("cp.async.wait_group 1;");
        } else {
            asm volatile("cp.async.wait_group 0;");
        }
        __syncthreads();   // KV(j) visible to all

        uint32_t kB = kBase0 + buf * (64 * 128);
        uint32_t vB = vBase0 + buf * (64 * 128);

        // ---- S = Q @ K^T ----
        float s[8][4];
#pragma unroll
        for (int nt = 0; nt < 8; nt++)
#pragma unroll
            for (int i = 0; i < 4; i++) s[nt][i] = 0.f;
#pragma unroll
        for (int kk = 0; kk < 4; kk++) {
            uint32_t bfr[8][2];
#pragma unroll
            for (int bb = 0; bb < 4; bb++) {
                int row = bb * 16 + rowBK_off;
                int ch = 2 * kk + bKsel;
                uint32_t t[4];
                ldsm4(t, kB + row * 128 + (((ch ^ (row & 7)) & 7) << 4));
                bfr[bb * 2 + 0][0] = t[0];
                bfr[bb * 2 + 0][1] = t[1];
                bfr[bb * 2 + 1][0] = t[2];
                bfr[bb * 2 + 1][1] = t[3];
            }
#pragma unroll
            for (int nt = 0; nt < 8; nt++)
                mma_f16(s[nt], qfr[kk], bfr[nt]);
        }

        // ---- scale + causal mask ----
#pragma unroll
        for (int nt = 0; nt < 8; nt++) {
#pragma unroll
            for (int i = 0; i < 4; i++) s[nt][i] *= scale;
        }
        if (j == qi) {
#pragma unroll
            for (int nt = 0; nt < 8; nt++) {
                int col0 = nt * 8 + tg * 2;
                if (col0 > rq0)     s[nt][0] = -INFINITY;
                if (col0 + 1 > rq0) s[nt][1] = -INFINITY;
                if (col0 > rq0 + 8)     s[nt][2] = -INFINITY;
                if (col0 + 1 > rq0 + 8) s[nt][3] = -INFINITY;
            }
        }

        // ---- online softmax ----
        float mx0 = -INFINITY, mx1 = -INFINITY;
#pragma unroll
        for (int nt = 0; nt < 8; nt++) {
            mx0 = fmaxf(mx0, fmaxf(s[nt][0], s[nt][1]));
            mx1 = fmaxf(mx1, fmaxf(s[nt][2], s[nt][3]));
        }
        mx0 = fmaxf(mx0, __shfl_xor_sync(0xffffffffu, mx0, 1, 4));
        mx0 = fmaxf(mx0, __shfl_xor_sync(0xffffffffu, mx0, 2, 4));
        mx1 = fmaxf(mx1, __shfl_xor_sync(0xffffffffu, mx1, 1, 4));
        mx1 = fmaxf(mx1, __shfl_xor_sync(0xffffffffu, mx1, 2, 4));
        float mn0 = fmaxf(m0, mx0), mn1 = fmaxf(m1, mx1);
        float a0 = expf(m0 - mn0), a1 = expf(m1 - mn1);
        m0 = mn0; m1 = mn1;

        float ls0 = 0.f, ls1 = 0.f;
        uint32_t pa[4][4];
#pragma unroll
        for (int nt = 0; nt < 8; nt++) {
            float p0 = expf(s[nt][0] - mn0);
            float p1 = expf(s[nt][1] - mn0);
            float p2 = expf(s[nt][2] - mn1);
            float p3 = expf(s[nt][3] - mn1);
            ls0 += p0 + p1;
            ls1 += p2 + p3;
            __half2 hA = __floats2half2_rn(p0, p1);
            __half2 hB = __floats2half2_rn(p2, p3);
            int t = nt >> 1, hi = nt & 1;
            pa[t][hi * 2 + 0] = *reinterpret_cast<uint32_t*>(&hA);
            pa[t][hi * 2 + 1] = *reinterpret_cast<uint32_t*>(&hB);
        }
        ls0 += __shfl_xor_sync(0xffffffffu, ls0, 1, 4);
        ls0 += __shfl_xor_sync(0xffffffffu, ls0, 2, 4);
        ls1 += __shfl_xor_sync(0xffffffffu, ls1, 1, 4);
        ls1 += __shfl_xor_sync(0xffffffffu, ls1, 2, 4);
        l0 = l0 * a0 + ls0;
        l1 = l1 * a1 + ls1;

#pragma unroll
        for (int nt = 0; nt < 8; nt++) {
            o[nt][0] *= a0; o[nt][1] *= a0;
            o[nt][2] *= a1; o[nt][3] *= a1;
        }

        // ---- O += P @ V ----
#pragma unroll
        for (int t = 0; t < 4; t++) {       // key tiles of 16
            uint32_t vfr[8][2];
#pragma unroll
            for (int bb = 0; bb < 4; bb++) {  // dim-tile pairs
                int row = t * 16 + rowV_off;
                int ch = 2 * bb + vNsel;
                uint32_t r4[4];
                ldsm4t(r4, vB + row * 128 + (((ch ^ (row & 7)) & 7) << 4));
                vfr[bb * 2 + 0][0] = r4[0];
                vfr[bb * 2 + 0][1] = r4[1];
                vfr[bb * 2 + 1][0] = r4[2];
                vfr[bb * 2 + 1][1] = r4[3];
            }
#pragma unroll
            for (int nd = 0; nd < 8; nd++)
                mma_f16(o[nd], pa[t], vfr[nd]);
        }
    }

    // ---- write O (half) ----
    float inv0 = 1.0f / l0, inv1 = 1.0f / l1;
    size_t rbase = (size_t)(b * Sq + qi * 64 + warp * 16 + g) * Dm + h * HDm;
#pragma unroll
    for (int nd = 0; nd < 8; nd++) {
        int col = nd * 8 + tg * 2;
        *reinterpret_cast<__half2*>(Og + rbase + col) =
            __floats2half2_rn(o[nd][0] * inv0, o[nd][1] * inv0);
        *reinterpret_cast<__half2*>(Og + rbase + 8 * Dm + col) =
            __floats2half2_rn(o[nd][2] * inv1, o[nd][3] * inv1);
    }
}

// ---------------------------------------------------------------------------
extern "C" void kernel_launch(void* const* d_in, const int* in_sizes, int n_in,
                              void* d_out, int out_size) {
    const int*   tokens  = (const int*)d_in[0];
    const float* tok_emb = (const float*)d_in[1];
    const float* pos_emb = (const float*)d_in[2];
    const float* ln1_g = (const float*)d_in[3];
    const float* ln1_b = (const float*)d_in[4];
    const float* wq = (const float*)d_in[5];
    const float* wk = (const float*)d_in[6];
    const float* wv = (const float*)d_in[7];
    const float* wo = (const float*)d_in[8];
    const float* ln2_g = (const float*)d_in[9];
    const float* ln2_b = (const float*)d_in[10];
    const float* w1 = (const float*)d_in[11];
    const float* b1 = (const float*)d_in[12];
    const float* w2 = (const float*)d_in[13];
    const float* b2 = (const float*)d_in[14];
    const float* lnf_g = (const float*)d_in[15];
    const float* lnf_b = (const float*)d_in[16];
    float* out = (float*)d_out;

    float *px;
    __half *ph, *pq, *pk, *pv, *pa, *pf, *pwqt, *pwkt, *pwvt, *pwot, *pw1t, *pw2t, *pembh;
    cudaGetSymbolAddress((void**)&px, g_x);
    cudaGetSymbolAddress((void**)&ph, g_h);
    cudaGetSymbolAddress((void**)&pq, g_q);
    cudaGetSymbolAddress((void**)&pk, g_k);
    cudaGetSymbolAddress((void**)&pv, g_v);
    cudaGetSymbolAddress((void**)&pa, g_att);
    cudaGetSymbolAddress((void**)&pf, g_ff);
    cudaGetSymbolAddress((void**)&pwqt, g_wqt);
    cudaGetSymbolAddress((void**)&pwkt, g_wkt);
    cudaGetSymbolAddress((void**)&pwvt, g_wvt);
    cudaGetSymbolAddress((void**)&pwot, g_wot);
    cudaGetSymbolAddress((void**)&pw1t, g_w1t);
    cudaGetSymbolAddress((void**)&pw2t, g_w2t);
    cudaGetSymbolAddress((void**)&pembh, g_embh);

    cudaFuncSetAttribute((const void*)gemm_kernel<0, false, true, float>,  cudaFuncAttributeMaxDynamicSharedMemorySize, SMEM_TOTAL);
    cudaFuncSetAttribute((const void*)gemm_kernel<1, true, false, float>,  cudaFuncAttributeMaxDynamicSharedMemorySize, SMEM_TOTAL);
    cudaFuncSetAttribute((const void*)gemm_kernel<2, true, false, __half>, cudaFuncAttributeMaxDynamicSharedMemorySize, SMEM_TOTAL);
    cudaFuncSetAttribute((const void*)gemm_kernel<3, true, false, float>,  cudaFuncAttributeMaxDynamicSharedMemorySize, SMEM_TOTAL);
    cudaFuncSetAttribute((const void*)qkv_kernel,                          cudaFuncAttributeMaxDynamicSharedMemorySize, SMEM_TOTAL);

    dim3 gD(Dm / 128, MROWS / 128);
    dim3 gQKV(Dm / 128, MROWS / 128, 3);
    dim3 gFF(FFd / 128, MROWS / 128);
    dim3 gAttn(Sq / 64, Hh, Bz);

    // Launch order: #0 t4, #1 embed_ln(l0), #2 qkv(l0), #3 attn(l0)  <- ncu hits #3
    dim3 gT4(Dm / 32, Dm / 32, 4 * Ll);
    transpose4_h_kernel<<<gT4, 256>>>(wq, wk, wv, wo, pwqt, pwkt, pwvt, pwot);
    embed_ln_kernel<<<MROWS, 256>>>(tokens, tok_emb, pos_emb, ln1_g, ln1_b);
    qkv_kernel<<<gQKV, 256, SMEM_TOTAL>>>(ph, pwqt, pwkt, pwvt, pq, pk, pv);
    attn_kernel<<<gAttn, 128>>>(pq, pk, pv, pa);

    dim3 gT1(FFd / 32, Dm / 32, Ll);
    transpose_h_kernel<<<gT1, 256>>>(w1, pw1t, Dm, FFd);
    dim3 gT2(Dm / 32, FFd / 32, Ll);
    transpose_h_kernel<<<gT2, 256>>>(w2, pw2t, FFd, Dm);
    emb_h_kernel<<<Vv, 256>>>(tok_emb, pembh);

    for (int l = 0; l < Ll; l++) {
        const __half* lWqt = pwqt + (size_t)l * Dm * Dm;
        const __half* lWkt = pwkt + (size_t)l * Dm * Dm;
        const __half* lWvt = pwvt + (size_t)l * Dm * Dm;
        const __half* lWot = pwot + (size_t)l * Dm * Dm;
        const __half* lW1t = pw1t + (size_t)l * Dm * FFd;
        const __half* lW2t = pw2t + (size_t)l * FFd * Dm;
        const float* lB1 = b1 + (size_t)l * FFd;
        const float* lB2 = b2 + (size_t)l * Dm;

        if (l > 0) {
            ln_kernel<<<MROWS, 256>>>(px, ln1_g + (size_t)l * Dm, ln1_b + (size_t)l * Dm, ph);
            qkv_kernel<<<gQKV, 256, SMEM_TOTAL>>>(ph, lWqt, lWkt, lWvt, pq, pk, pv);
            attn_kernel<<<gAttn, 128>>>(pq, pk, pv, pa);
        }
        gemm_kernel<1, true, false, float><<<gD, 256, SMEM_TOTAL>>>(pa, lWot, nullptr, px, px, MROWS, Dm, Dm);
        ln_kernel<<<MROWS, 256>>>(px, ln2_g + (size_t)l * Dm, ln2_b + (size_t)l * Dm, ph);
        gemm_kernel<2, true, false, __half><<<gFF, 256, SMEM_TOTAL>>>(ph, lW1t, lB1, nullptr, pf, MROWS, FFd, Dm);
        gemm_kernel<3, true, false, float><<<gD, 256, SMEM_TOTAL>>>(pf, lW2t, lB2, px, px, MROWS, Dm, FFd);
    }

    ln_kernel<<<MROWS, 256>>>(px, lnf_g, lnf_b, ph);
    dim3 gLog(MROWS / 128, (Vv + 127) / 128);
    gemm_kernel<0, false, true, float><<<gLog, 256, SMEM_TOTAL>>>(ph, pembh, nullptr, nullptr, out, MROWS, Vv, Dm);
}

// round 12
// speedup vs baseline: 6.2387x; 1.4875x over previous
#include <cuda_runtime.h>
#include <cuda_fp16.h>
#include <math.h>
#include <stdint.h>

#define Bz 2
#define Sq 1024
#define Dm 1024
#define Hh 16
#define Ll 6
#define Vv 50257
#define HDm 64
#define MROWS (Bz * Sq)
#define FFd (4 * Dm)

__device__ float  g_x[MROWS * Dm];              // fp32 residual stream
__device__ __half g_h[MROWS * Dm];
__device__ __half g_q[MROWS * Dm];
__device__ __half g_k[MROWS * Dm];
__device__ __half g_v[MROWS * Dm];
__device__ __half g_att[MROWS * Dm];
__device__ __half g_ff[MROWS * FFd];
__device__ __half g_wqt[Ll * Dm * Dm];
__device__ __half g_wkt[Ll * Dm * Dm];
__device__ __half g_wvt[Ll * Dm * Dm];
__device__ __half g_wot[Ll * Dm * Dm];
__device__ __half g_w1t[(size_t)Ll * Dm * FFd];
__device__ __half g_w2t[(size_t)Ll * FFd * Dm];
__device__ __half g_embh[(size_t)Vv * Dm];

__device__ __forceinline__ void cpasync16(void* sdst, const void* gsrc) {
    uint32_t d = (uint32_t)__cvta_generic_to_shared(sdst);
    asm volatile("cp.async.cg.shared.global [%0], [%1], 16;" :: "r"(d), "l"(gsrc));
}
__device__ __forceinline__ void mma_f16(float* c, const uint32_t* a, const uint32_t* b) {
    asm volatile(
        "mma.sync.aligned.m16n8k16.row.col.f32.f16.f16.f32 "
        "{%0,%1,%2,%3}, {%4,%5,%6,%7}, {%8,%9}, {%0,%1,%2,%3};"
        : "+f"(c[0]), "+f"(c[1]), "+f"(c[2]), "+f"(c[3])
        : "r"(a[0]), "r"(a[1]), "r"(a[2]), "r"(a[3]), "r"(b[0]), "r"(b[1]));
}
__device__ __forceinline__ void ldsm4(uint32_t* r, uint32_t addr) {
    asm volatile("ldmatrix.sync.aligned.m8n8.x4.shared.b16 {%0,%1,%2,%3}, [%4];"
                 : "=r"(r[0]), "=r"(r[1]), "=r"(r[2]), "=r"(r[3]) : "r"(addr));
}
__device__ __forceinline__ void ldsm4t(uint32_t* r, uint32_t addr) {
    asm volatile("ldmatrix.sync.aligned.m8n8.x4.trans.shared.b16 {%0,%1,%2,%3}, [%4];"
                 : "=r"(r[0]), "=r"(r[1]), "=r"(r[2]), "=r"(r[3]) : "r"(addr));
}
__device__ __forceinline__ void store2(__half* C, size_t idx, float v0, float v1) {
    *reinterpret_cast<__half2*>(C + idx) = __floats2half2_rn(v0, v1);
}
__device__ __forceinline__ void store2(float* C, size_t idx, float v0, float v1) {
    float2 o; o.x = v0; o.y = v1;
    *reinterpret_cast<float2*>(C + idx) = o;
}

// ---------------------------------------------------------------------------
__global__ __launch_bounds__(256) void embed_ln_kernel(const int* __restrict__ tokens,
                                                       const float* __restrict__ tok_emb,
                                                       const float* __restrict__ pos_emb,
                                                       const float* __restrict__ gw,
                                                       const float* __restrict__ bw) {
    int row = blockIdx.x, tid = threadIdx.x;
    int s = row % Sq;
    int tok = tokens[row];
    const float* te = tok_emb + (size_t)tok * Dm;
    const float* pe = pos_emb + (size_t)s * Dm;
    float v[4], sm = 0.f, s2 = 0.f;
#pragma unroll
    for (int i = 0; i < 4; i++) {
        int col = tid + i * 256;
        v[i] = te[col] + pe[col];
        g_x[(size_t)row * Dm + col] = v[i];
        sm += v[i]; s2 += v[i] * v[i];
    }
#pragma unroll
    for (int o = 16; o > 0; o >>= 1) {
        sm += __shfl_xor_sync(0xffffffffu, sm, o);
        s2 += __shfl_xor_sync(0xffffffffu, s2, o);
    }
    __shared__ float ws[8], ws2[8];
    int w = tid >> 5, l = tid & 31;
    if (l == 0) { ws[w] = sm; ws2[w] = s2; }
    __syncthreads();
    sm = 0.f; s2 = 0.f;
#pragma unroll
    for (int i = 0; i < 8; i++) { sm += ws[i]; s2 += ws2[i]; }
    float mean = sm * (1.0f / Dm);
    float var = s2 * (1.0f / Dm) - mean * mean;
    float rstd = rsqrtf(var + 1e-5f);
#pragma unroll
    for (int i = 0; i < 4; i++) {
        int col = tid + i * 256;
        g_h[(size_t)row * Dm + col] = __float2half((v[i] - mean) * rstd * gw[col] + bw[col]);
    }
}

__global__ __launch_bounds__(256) void transpose4_h_kernel(
    const float* __restrict__ wq, const float* __restrict__ wk,
    const float* __restrict__ wv, const float* __restrict__ wo,
    __half* __restrict__ oq, __half* __restrict__ ok,
    __half* __restrict__ ov, __half* __restrict__ oo) {
    __shared__ float t[32][33];
    int which = blockIdx.z / Ll, l = blockIdx.z % Ll;
    const float* W = (which == 0) ? wq : (which == 1) ? wk : (which == 2) ? wv : wo;
    __half* O = (which == 0) ? oq : (which == 1) ? ok : (which == 2) ? ov : oo;
    const float* Wl = W + (size_t)l * Dm * Dm;
    __half* Ol = O + (size_t)l * Dm * Dm;
    int n0 = blockIdx.x * 32, k0 = blockIdx.y * 32;
    int tx = threadIdx.x & 31, ty = threadIdx.x >> 5;
#pragma unroll
    for (int i = 0; i < 32; i += 8)
        t[ty + i][tx] = Wl[(size_t)(k0 + ty + i) * Dm + n0 + tx];
    __syncthreads();
#pragma unroll
    for (int i = 0; i < 32; i += 8)
        Ol[(size_t)(n0 + ty + i) * Dm + k0 + tx] = __float2half(t[tx][ty + i]);
}

__global__ __launch_bounds__(256) void transpose_h_kernel(const float* __restrict__ W,
                                                          __half* __restrict__ WT, int K, int N) {
    __shared__ float t[32][33];
    const float* Wl = W + (size_t)blockIdx.z * K * N;
    __half* WTl = WT + (size_t)blockIdx.z * K * N;
    int n0 = blockIdx.x * 32, k0 = blockIdx.y * 32;
    int tx = threadIdx.x & 31, ty = threadIdx.x >> 5;
#pragma unroll
    for (int i = 0; i < 32; i += 8)
        t[ty + i][tx] = Wl[(size_t)(k0 + ty + i) * N + n0 + tx];
    __syncthreads();
#pragma unroll
    for (int i = 0; i < 32; i += 8)
        WTl[(size_t)(n0 + ty + i) * K + k0 + tx] = __float2half(t[tx][ty + i]);
}

__global__ __launch_bounds__(256) void emb_h_kernel(const float* __restrict__ E, __half* __restrict__ O) {
    size_t base = (size_t)blockIdx.x * Dm + threadIdx.x * 4;
    float4 v = *reinterpret_cast<const float4*>(E + base);
    __half2 h0 = __floats2half2_rn(v.x, v.y);
    __half2 h1 = __floats2half2_rn(v.z, v.w);
    uint2 u;
    u.x = *reinterpret_cast<uint32_t*>(&h0);
    u.y = *reinterpret_cast<uint32_t*>(&h1);
    *reinterpret_cast<uint2*>(O + base) = u;
}

__global__ __launch_bounds__(256) void ln_kernel(const float* __restrict__ x,
                                                 const float* __restrict__ gw,
                                                 const float* __restrict__ bw,
                                                 __half* __restrict__ out) {
    int row = blockIdx.x, tid = threadIdx.x;
    const float* xr = x + (size_t)row * Dm;
    float v[4], s = 0.f, s2 = 0.f;
#pragma unroll
    for (int i = 0; i < 4; i++) { v[i] = xr[tid + i * 256]; s += v[i]; s2 += v[i] * v[i]; }
#pragma unroll
    for (int o = 16; o > 0; o >>= 1) {
        s += __shfl_xor_sync(0xffffffffu, s, o);
        s2 += __shfl_xor_sync(0xffffffffu, s2, o);
    }
    __shared__ float ws[8], ws2[8];
    int w = tid >> 5, l = tid & 31;
    if (l == 0) { ws[w] = s; ws2[w] = s2; }
    __syncthreads();
    s = 0.f; s2 = 0.f;
#pragma unroll
    for (int i = 0; i < 8; i++) { s += ws[i]; s2 += ws2[i]; }
    float mean = s * (1.0f / Dm);
    float var = s2 * (1.0f / Dm) - mean * mean;
    float rstd = rsqrtf(var + 1e-5f);
    __half* orow = out + (size_t)row * Dm;
#pragma unroll
    for (int i = 0; i < 4; i++) {
        int col = tid + i * 256;
        orow[col] = __float2half((v[i] - mean) * rstd * gw[col] + bw[col]);
    }
}

// ---------------------------------------------------------------------------
// FP16 m16n8k16 GEMM, ldmatrix, templated CTA M-tile.
// MT = m16 tiles per warp: 4 -> CTA 128x128, 2 -> CTA 64x128.
// 3-stage cp.async, 256 threads (8 warps, 2(M) x 4(N)), warp tile (MT*16) x 32.
// ---------------------------------------------------------------------------
#define SMEM_MT4 (3 * (128 * 128 + 128 * 128))   // 98304
#define SMEM_MT2 (3 * (64 * 128 + 128 * 128))    // 73728

template <int OP, bool VEC, bool SWAP, int MT, typename OutT>
__device__ __forceinline__ void gemm_body(const __half* __restrict__ A, const __half* __restrict__ Bt,
                                          const float* __restrict__ bias, const float* __restrict__ res,
                                          OutT* __restrict__ C, int M, int N, int K) {
    extern __shared__ char smem[];
    constexpr int CTAM = MT * 32;                      // 128 or 64
    constexpr int STG = CTAM * 128 + 128 * 128;        // stage bytes
    const int m0 = (SWAP ? blockIdx.x : blockIdx.y) * CTAM;
    const int n0 = (SWAP ? blockIdx.y : blockIdx.x) * 128;
    int tid = threadIdx.x, warp = tid >> 5, lane = tid & 31;
    int g = lane >> 2, tg = lane & 3;
    int wm = warp & 1, wn = warp >> 1;

    float acc[MT][4][4];
#pragma unroll
    for (int mt = 0; mt < MT; mt++)
#pragma unroll
        for (int nt = 0; nt < 4; nt++)
#pragma unroll
            for (int i = 0; i < 4; i++) acc[mt][nt][i] = 0.f;

    const int KT = K / 64;
    uint32_t smemBase = (uint32_t)__cvta_generic_to_shared(smem);

    int rowA_off = wm * (MT * 16) + ((lane >> 3) & 1) * 8 + (lane & 7);
    int aKsel = lane >> 4;
    int rowB_off = wn * 32 + (lane >> 4) * 8 + (lane & 7);
    int bKsel = (lane >> 3) & 1;

    auto loadStage = [&](int stg) {
        char* base = smem + (stg % 3) * STG;
        char* sa = base;
        char* sbf = base + CTAM * 128;
        const __half* Ak = A + (size_t)m0 * K + stg * 64;
        const __half* Bk = Bt + stg * 64;
#pragma unroll
        for (int p = 0; p < MT; p++) {                 // CTAM*8/256 = MT passes
            int id = tid + p * 256, r = id >> 3, c = id & 7;
            cpasync16(sa + r * 128 + ((c ^ (r & 7)) * 16), Ak + (size_t)r * K + c * 8);
        }
#pragma unroll
        for (int p = 0; p < 4; p++) {
            int id = tid + p * 256, r = id >> 3, c = id & 7;
            int n = n0 + r; if (n >= N) n = N - 1;
            cpasync16(sbf + r * 128 + ((c ^ (r & 7)) * 16), Bk + (size_t)n * K + c * 8);
        }
        asm volatile("cp.async.commit_group;");
    };

    loadStage(0);
    loadStage(1);

    for (int j = 0; j < KT; j++) {
        if (j + 1 < KT) asm volatile("cp.async.wait_group 1;");
        else            asm volatile("cp.async.wait_group 0;");
        __syncthreads();
        if (j + 2 < KT) loadStage(j + 2);

        uint32_t aBase = smemBase + (j % 3) * STG;
        uint32_t bBase = aBase + CTAM * 128;

#pragma unroll
        for (int kk = 0; kk < 4; kk++) {
            uint32_t afr[MT][4];
#pragma unroll
            for (int mt = 0; mt < MT; mt++) {
                int row = rowA_off + mt * 16;
                int ch = 2 * kk + aKsel;
                ldsm4(afr[mt], aBase + row * 128 + (((ch ^ (row & 7)) & 7) << 4));
            }
            uint32_t bfr[4][2];
#pragma unroll
            for (int bb = 0; bb < 2; bb++) {
                int row = rowB_off + bb * 16;
                int ch = 2 * kk + bKsel;
                uint32_t t[4];
                ldsm4(t, bBase + row * 128 + (((ch ^ (row & 7)) & 7) << 4));
                bfr[bb * 2 + 0][0] = t[0];
                bfr[bb * 2 + 0][1] = t[1];
                bfr[bb * 2 + 1][0] = t[2];
                bfr[bb * 2 + 1][1] = t[3];
            }
#pragma unroll
            for (int mt = 0; mt < MT; mt++)
#pragma unroll
                for (int nt = 0; nt < 4; nt++)
                    mma_f16(acc[mt][nt], afr[mt], bfr[nt]);
        }
    }

#pragma unroll
    for (int mt = 0; mt < MT; mt++) {
#pragma unroll
        for (int half = 0; half < 2; half++) {
            int m = m0 + wm * (MT * 16) + mt * 16 + g + half * 8;
#pragma unroll
            for (int nt = 0; nt < 4; nt++) {
                int col = n0 + wn * 32 + nt * 8 + tg * 2;
                float v0 = acc[mt][nt][half * 2 + 0];
                float v1 = acc[mt][nt][half * 2 + 1];
                if (OP == 2 || OP == 3) { v0 += bias[col]; v1 += bias[col + 1]; }
                if (OP == 2) {
                    v0 = 0.5f * v0 * (1.0f + erff(v0 * 0.70710678118654752f));
                    v1 = 0.5f * v1 * (1.0f + erff(v1 * 0.70710678118654752f));
                }
                if (OP == 1 || OP == 3) {
                    float2 r = *reinterpret_cast<const float2*>(res + (size_t)m * N + col);
                    v0 += r.x; v1 += r.y;
                }
                if (VEC) {
                    store2(C, (size_t)m * N + col, v0, v1);
                } else {
                    if (col < N)     C[(size_t)m * N + col]     = (OutT)v0;
                    if (col + 1 < N) C[(size_t)m * N + col + 1] = (OutT)v1;
                }
            }
        }
    }
}

template <int OP, bool VEC, bool SWAP, int MT, typename OutT>
__global__ __launch_bounds__(256, 2) void gemm_kernel(const __half* __restrict__ A, const __half* __restrict__ Bt,
                                                      const float* __restrict__ bias, const float* __restrict__ res,
                                                      OutT* __restrict__ C, int M, int N, int K) {
    gemm_body<OP, VEC, SWAP, MT, OutT>(A, Bt, bias, res, C, M, N, K);
}

__global__ __launch_bounds__(256, 2) void qkv_kernel(const __half* __restrict__ A, const __half* __restrict__ Wqt,
                                                     const __half* __restrict__ Wkt, const __half* __restrict__ Wvt,
                                                     __half* __restrict__ Qo, __half* __restrict__ Ko,
                                                     __half* __restrict__ Vo) {
    const __half* Bt = (blockIdx.z == 0) ? Wqt : (blockIdx.z == 1 ? Wkt : Wvt);
    __half* C = (blockIdx.z == 0) ? Qo : (blockIdx.z == 1 ? Ko : Vo);
    gemm_body<0, true, false, 2, __half>(A, Bt, nullptr, nullptr, C, MROWS, Dm, Dm);
}

// ---------------------------------------------------------------------------
// Tensor-core flash attention (unchanged from round 11).
// ---------------------------------------------------------------------------
__global__ __launch_bounds__(128) void attn_kernel(const __half* __restrict__ Qg,
                                                   const __half* __restrict__ Kg,
                                                   const __half* __restrict__ Vg,
                                                   __half* __restrict__ Og) {
    __shared__ __align__(128) __half Qs[64 * 64];
    __shared__ __align__(128) __half Ks[2][64 * 64];
    __shared__ __align__(128) __half Vs[2][64 * 64];

    int b = blockIdx.z, h = blockIdx.y, qi = blockIdx.x;
    int tid = threadIdx.x, warp = tid >> 5, lane = tid & 31;
    int g = lane >> 2, tg = lane & 3;

    uint32_t qBase = (uint32_t)__cvta_generic_to_shared(Qs);
    uint32_t kBase0 = (uint32_t)__cvta_generic_to_shared(Ks[0]);
    uint32_t vBase0 = (uint32_t)__cvta_generic_to_shared(Vs[0]);

    {
        const __half* Qp = Qg + ((size_t)(b * Sq + qi * 64) * Dm) + h * HDm;
#pragma unroll
        for (int p = 0; p < 4; p++) {
            int id = tid + p * 128, r = id >> 3, c = id & 7;
            cpasync16((char*)Qs + r * 128 + ((c ^ (r & 7)) * 16), Qp + (size_t)r * Dm + c * 8);
        }
        const __half* Kp = Kg + ((size_t)(b * Sq) * Dm) + h * HDm;
        const __half* Vp = Vg + ((size_t)(b * Sq) * Dm) + h * HDm;
#pragma unroll
        for (int p = 0; p < 4; p++) {
            int id = tid + p * 128, r = id >> 3, c = id & 7;
            cpasync16((char*)Ks[0] + r * 128 + ((c ^ (r & 7)) * 16), Kp + (size_t)r * Dm + c * 8);
            cpasync16((char*)Vs[0] + r * 128 + ((c ^ (r & 7)) * 16), Vp + (size_t)r * Dm + c * 8);
        }
        asm volatile("cp.async.commit_group;");
    }
    asm volatile("cp.async.wait_group 0;");
    __syncthreads();

    uint32_t qfr[4][4];
    {
        int rowA = warp * 16 + ((lane >> 3) & 1) * 8 + (lane & 7);
        int aKsel = lane >> 4;
#pragma unroll
        for (int kk = 0; kk < 4; kk++) {
            int ch = 2 * kk + aKsel;
            ldsm4(qfr[kk], qBase + rowA * 128 + (((ch ^ (rowA & 7)) & 7) << 4));
        }
    }

    float m0 = -INFINITY, m1 = -INFINITY, l0 = 0.f, l1 = 0.f;
    float o[8][4];
#pragma unroll
    for (int nt = 0; nt < 8; nt++)
#pragma unroll
        for (int i = 0; i < 4; i++) o[nt][i] = 0.f;

    const float scale = 0.125f;
    int rowBK_off = (lane >> 4) * 8 + (lane & 7);
    int bKsel = (lane >> 3) & 1;
    int rowV_off = ((lane >> 3) & 1) * 8 + (lane & 7);
    int vNsel = lane >> 4;
    int rq0 = warp * 16 + g;

    for (int j = 0; j <= qi; j++) {
        int buf = j & 1;
        __syncthreads();
        bool pref = (j + 1 <= qi);
        if (pref) {
            int nb = buf ^ 1;
            const __half* Kp = Kg + ((size_t)(b * Sq + (j + 1) * 64) * Dm) + h * HDm;
            const __half* Vp = Vg + ((size_t)(b * Sq + (j + 1) * 64) * Dm) + h * HDm;
#pragma unroll
            for (int p = 0; p < 4; p++) {
                int id = tid + p * 128, r = id >> 3, c = id & 7;
                cpasync16((char*)Ks[nb] + r * 128 + ((c ^ (r & 7)) * 16), Kp + (size_t)r * Dm + c * 8);
                cpasync16((char*)Vs[nb] + r * 128 + ((c ^ (r & 7)) * 16), Vp + (size_t)r * Dm + c * 8);
            }
            asm volatile("cp.async.commit_group;");
            asm volatile("cp.async.wait_group 1;");
        } else {
            asm volatile("cp.async.wait_group 0;");
        }
        __syncthreads();

        uint32_t kB = kBase0 + buf * (64 * 128);
        uint32_t vB = vBase0 + buf * (64 * 128);

        float s[8][4];
#pragma unroll
        for (int nt = 0; nt < 8; nt++)
#pragma unroll
            for (int i = 0; i < 4; i++) s[nt][i] = 0.f;
#pragma unroll
        for (int kk = 0; kk < 4; kk++) {
            uint32_t bfr[8][2];
#pragma unroll
            for (int bb = 0; bb < 4; bb++) {
                int row = bb * 16 + rowBK_off;
                int ch = 2 * kk + bKsel;
                uint32_t t[4];
                ldsm4(t, kB + row * 128 + (((ch ^ (row & 7)) & 7) << 4));
                bfr[bb * 2 + 0][0] = t[0];
                bfr[bb * 2 + 0][1] = t[1];
                bfr[bb * 2 + 1][0] = t[2];
                bfr[bb * 2 + 1][1] = t[3];
            }
#pragma unroll
            for (int nt = 0; nt < 8; nt++)
                mma_f16(s[nt], qfr[kk], bfr[nt]);
        }

#pragma unroll
        for (int nt = 0; nt < 8; nt++) {
#pragma unroll
            for (int i = 0; i < 4; i++) s[nt][i] *= scale;
        }
        if (j == qi) {
#pragma unroll
            for (int nt = 0; nt < 8; nt++) {
                int col0 = nt * 8 + tg * 2;
                if (col0 > rq0)     s[nt][0] = -INFINITY;
                if (col0 + 1 > rq0) s[nt][1] = -INFINITY;
                if (col0 > rq0 + 8)     s[nt][2] = -INFINITY;
                if (col0 + 1 > rq0 + 8) s[nt][3] = -INFINITY;
            }
        }

        float mx0 = -INFINITY, mx1 = -INFINITY;
#pragma unroll
        for (int nt = 0; nt < 8; nt++) {
            mx0 = fmaxf(mx0, fmaxf(s[nt][0], s[nt][1]));
            mx1 = fmaxf(mx1, fmaxf(s[nt][2], s[nt][3]));
        }
        mx0 = fmaxf(mx0, __shfl_xor_sync(0xffffffffu, mx0, 1, 4));
        mx0 = fmaxf(mx0, __shfl_xor_sync(0xffffffffu, mx0, 2, 4));
        mx1 = fmaxf(mx1, __shfl_xor_sync(0xffffffffu, mx1, 1, 4));
        mx1 = fmaxf(mx1, __shfl_xor_sync(0xffffffffu, mx1, 2, 4));
        float mn0 = fmaxf(m0, mx0), mn1 = fmaxf(m1, mx1);
        float a0 = expf(m0 - mn0), a1 = expf(m1 - mn1);
        m0 = mn0; m1 = mn1;

        float ls0 = 0.f, ls1 = 0.f;
        uint32_t pa[4][4];
#pragma unroll
        for (int nt = 0; nt < 8; nt++) {
            float p0 = expf(s[nt][0] - mn0);
            float p1 = expf(s[nt][1] - mn0);
            float p2 = expf(s[nt][2] - mn1);
            float p3 = expf(s[nt][3] - mn1);
            ls0 += p0 + p1;
            ls1 += p2 + p3;
            __half2 hA = __floats2half2_rn(p0, p1);
            __half2 hB = __floats2half2_rn(p2, p3);
            int t = nt >> 1, hi = nt & 1;
            pa[t][hi * 2 + 0] = *reinterpret_cast<uint32_t*>(&hA);
            pa[t][hi * 2 + 1] = *reinterpret_cast<uint32_t*>(&hB);
        }
        ls0 += __shfl_xor_sync(0xffffffffu, ls0, 1, 4);
        ls0 += __shfl_xor_sync(0xffffffffu, ls0, 2, 4);
        ls1 += __shfl_xor_sync(0xffffffffu, ls1, 1, 4);
        ls1 += __shfl_xor_sync(0xffffffffu, ls1, 2, 4);
        l0 = l0 * a0 + ls0;
        l1 = l1 * a1 + ls1;

#pragma unroll
        for (int nt = 0; nt < 8; nt++) {
            o[nt][0] *= a0; o[nt][1] *= a0;
            o[nt][2] *= a1; o[nt][3] *= a1;
        }

#pragma unroll
        for (int t = 0; t < 4; t++) {
            uint32_t vfr[8][2];
#pragma unroll
            for (int bb = 0; bb < 4; bb++) {
                int row = t * 16 + rowV_off;
                int ch = 2 * bb + vNsel;
                uint32_t r4[4];
                ldsm4t(r4, vB + row * 128 + (((ch ^ (row & 7)) & 7) << 4));
                vfr[bb * 2 + 0][0] = r4[0];
                vfr[bb * 2 + 0][1] = r4[1];
                vfr[bb * 2 + 1][0] = r4[2];
                vfr[bb * 2 + 1][1] = r4[3];
            }
#pragma unroll
            for (int nd = 0; nd < 8; nd++)
                mma_f16(o[nd], pa[t], vfr[nd]);
        }
    }

    float inv0 = 1.0f / l0, inv1 = 1.0f / l1;
    size_t rbase = (size_t)(b * Sq + qi * 64 + warp * 16 + g) * Dm + h * HDm;
#pragma unroll
    for (int nd = 0; nd < 8; nd++) {
        int col = nd * 8 + tg * 2;
        *reinterpret_cast<__half2*>(Og + rbase + col) =
            __floats2half2_rn(o[nd][0] * inv0, o[nd][1] * inv0);
        *reinterpret_cast<__half2*>(Og + rbase + 8 * Dm + col) =
            __floats2half2_rn(o[nd][2] * inv1, o[nd][3] * inv1);
    }
}

// ---------------------------------------------------------------------------
extern "C" void kernel_launch(void* const* d_in, const int* in_sizes, int n_in,
                              void* d_out, int out_size) {
    const int*   tokens  = (const int*)d_in[0];
    const float* tok_emb = (const float*)d_in[1];
    const float* pos_emb = (const float*)d_in[2];
    const float* ln1_g = (const float*)d_in[3];
    const float* ln1_b = (const float*)d_in[4];
    const float* wq = (const float*)d_in[5];
    const float* wk = (const float*)d_in[6];
    const float* wv = (const float*)d_in[7];
    const float* wo = (const float*)d_in[8];
    const float* ln2_g = (const float*)d_in[9];
    const float* ln2_b = (const float*)d_in[10];
    const float* w1 = (const float*)d_in[11];
    const float* b1 = (const float*)d_in[12];
    const float* w2 = (const float*)d_in[13];
    const float* b2 = (const float*)d_in[14];
    const float* lnf_g = (const float*)d_in[15];
    const float* lnf_b = (const float*)d_in[16];
    float* out = (float*)d_out;

    float *px;
    __half *ph, *pq, *pk, *pv, *pa, *pf, *pwqt, *pwkt, *pwvt, *pwot, *pw1t, *pw2t, *pembh;
    cudaGetSymbolAddress((void**)&px, g_x);
    cudaGetSymbolAddress((void**)&ph, g_h);
    cudaGetSymbolAddress((void**)&pq, g_q);
    cudaGetSymbolAddress((void**)&pk, g_k);
    cudaGetSymbolAddress((void**)&pv, g_v);
    cudaGetSymbolAddress((void**)&pa, g_att);
    cudaGetSymbolAddress((void**)&pf, g_ff);
    cudaGetSymbolAddress((void**)&pwqt, g_wqt);
    cudaGetSymbolAddress((void**)&pwkt, g_wkt);
    cudaGetSymbolAddress((void**)&pwvt, g_wvt);
    cudaGetSymbolAddress((void**)&pwot, g_wot);
    cudaGetSymbolAddress((void**)&pw1t, g_w1t);
    cudaGetSymbolAddress((void**)&pw2t, g_w2t);
    cudaGetSymbolAddress((void**)&pembh, g_embh);

    cudaFuncSetAttribute((const void*)gemm_kernel<0, false, true, 4, float>,  cudaFuncAttributeMaxDynamicSharedMemorySize, SMEM_MT4);
    cudaFuncSetAttribute((const void*)gemm_kernel<1, true, false, 2, float>,  cudaFuncAttributeMaxDynamicSharedMemorySize, SMEM_MT2);
    cudaFuncSetAttribute((const void*)gemm_kernel<2, true, false, 4, __half>, cudaFuncAttributeMaxDynamicSharedMemorySize, SMEM_MT4);
    cudaFuncSetAttribute((const void*)gemm_kernel<3, true, false, 2, float>,  cudaFuncAttributeMaxDynamicSharedMemorySize, SMEM_MT2);
    cudaFuncSetAttribute((const void*)qkv_kernel,                             cudaFuncAttributeMaxDynamicSharedMemorySize, SMEM_MT2);

    dim3 gD64(Dm / 128, MROWS / 64);          // (8,32) = 256 CTAs
    dim3 gQKV64(Dm / 128, MROWS / 64, 3);     // 768 CTAs
    dim3 gFF(FFd / 128, MROWS / 128);         // (32,16) = 512 CTAs
    dim3 gAttn(Sq / 64, Hh, Bz);

    // Launch order: #0 t4, #1 embed_ln(l0), #2 qkv(l0), #3 attn(l0)
    dim3 gT4(Dm / 32, Dm / 32, 4 * Ll);
    transpose4_h_kernel<<<gT4, 256>>>(wq, wk, wv, wo, pwqt, pwkt, pwvt, pwot);
    embed_ln_kernel<<<MROWS, 256>>>(tokens, tok_emb, pos_emb, ln1_g, ln1_b);
    qkv_kernel<<<gQKV64, 256, SMEM_MT2>>>(ph, pwqt, pwkt, pwvt, pq, pk, pv);
    attn_kernel<<<gAttn, 128>>>(pq, pk, pv, pa);

    dim3 gT1(FFd / 32, Dm / 32, Ll);
    transpose_h_kernel<<<gT1, 256>>>(w1, pw1t, Dm, FFd);
    dim3 gT2(Dm / 32, FFd / 32, Ll);
    transpose_h_kernel<<<gT2, 256>>>(w2, pw2t, FFd, Dm);
    emb_h_kernel<<<Vv, 256>>>(tok_emb, pembh);

    for (int l = 0; l < Ll; l++) {
        const __half* lWqt = pwqt + (size_t)l * Dm * Dm;
        const __half* lWkt = pwkt + (size_t)l * Dm * Dm;
        const __half* lWvt = pwvt + (size_t)l * Dm * Dm;
        const __half* lWot = pwot + (size_t)l * Dm * Dm;
        const __half* lW1t = pw1t + (size_t)l * Dm * FFd;
        const __half* lW2t = pw2t + (size_t)l * FFd * Dm;
        const float* lB1 = b1 + (size_t)l * FFd;
        const float* lB2 = b2 + (size_t)l * Dm;

        if (l > 0) {
            ln_kernel<<<MROWS, 256>>>(px, ln1_g + (size_t)l * Dm, ln1_b + (size_t)l * Dm, ph);
            qkv_kernel<<<gQKV64, 256, SMEM_MT2>>>(ph, lWqt, lWkt, lWvt, pq, pk, pv);
            attn_kernel<<<gAttn, 128>>>(pq, pk, pv, pa);
        }
        gemm_kernel<1, true, false, 2, float><<<gD64, 256, SMEM_MT2>>>(pa, lWot, nullptr, px, px, MROWS, Dm, Dm);
        ln_kernel<<<MROWS, 256>>>(px, ln2_g + (size_t)l * Dm, ln2_b + (size_t)l * Dm, ph);
        gemm_kernel<2, true, false, 4, __half><<<gFF, 256, SMEM_MT4>>>(ph, lW1t, lB1, nullptr, pf, MROWS, FFd, Dm);
        gemm_kernel<3, true, false, 2, float><<<gD64, 256, SMEM_MT2>>>(pf, lW2t, lB2, px, px, MROWS, Dm, FFd);
    }

    ln_kernel<<<MROWS, 256>>>(px, lnf_g, lnf_b, ph);
    dim3 gLog(MROWS / 128, (Vv + 127) / 128);
    gemm_kernel<0, false, true, 4, float><<<gLog, 256, SMEM_MT4>>>(ph, pembh, nullptr, nullptr, out, MROWS, Vv, Dm);
}